// round 11
// baseline (speedup 1.0000x reference)
#include <cuda_runtime.h>
#include <math.h>

// ---------------------------------------------------------------------------
// Problem constants
// ---------------------------------------------------------------------------
#define B_      32
#define N_      2048
#define M_      512            // N_/STRIDE
#define T_      (B_ * M_)      // 16384 targets
#define C_      64
#define KNN_    32
#define NJ_     768            // 4 slabs * 3 shells * 64 units
#define NPTS_   (B_ * N_)      // 65536

// Scratch (allowed: __device__ globals, no runtime allocation)
__device__ float g_A[(size_t)NPTS_ * NJ_];   // point-level transformed features
__device__ float g_Wbig[C_ * NJ_];           // repacked weights [c][(l,s,u)]
__device__ int   g_nbr[T_ * KNN_];           // neighbor indices, -1 padded
__device__ float g_H[B_ * 256];              // max-pooled features

// ---------------------------------------------------------------------------
// K0: repack W0..W3 -> Wbig[c][(l*3+s)*64+u] = W_l[(s*64+c)*64+u]; zero g_H
// ---------------------------------------------------------------------------
__global__ void prep_kernel(const float* __restrict__ W0, const float* __restrict__ W1,
                            const float* __restrict__ W2, const float* __restrict__ W3)
{
    int tid = blockIdx.x * blockDim.x + threadIdx.x;
    if (tid < B_ * 256) g_H[tid] = 0.0f;
    if (tid < C_ * NJ_) {
        int c = tid / NJ_;
        int j = tid - c * NJ_;
        int l = j / 192;
        int r = j - l * 192;
        int s = r >> 6;
        int u = r & 63;
        const float* W = (l == 0) ? W0 : (l == 1) ? W1 : (l == 2) ? W2 : W3;
        g_Wbig[tid] = W[(s * 64 + c) * 64 + u];
    }
}

// ---------------------------------------------------------------------------
// K1: KNN via radius filter + exact rank-select fallback.
// Correctness argument: neighbors with dist > RADIUS have weight exactly 0
// (mask dn<=1 in the reference), so when in-radius count <= 32 any top-32
// superset is equivalent; when count > 32 we exactly select the 32 smallest
// d2 (same as jax top_k on -d2).
// One warp per target; points of the batch staged in shared memory.
// ---------------------------------------------------------------------------
__global__ __launch_bounds__(256) void knn_kernel(const float* __restrict__ points)
{
    __shared__ float sp[N_ * 3];          // 24 KB
    __shared__ float sd2[8][256];         // 8 KB
    __shared__ int   sidx[8][256];        // 8 KB

    const int b = blockIdx.y;
    const float* pb = points + (size_t)b * N_ * 3;
    for (int i = threadIdx.x; i < N_ * 3; i += 256) sp[i] = pb[i];
    __syncthreads();

    const int warp = threadIdx.x >> 5;
    const int lane = threadIdx.x & 31;
    const int m = blockIdx.x * 8 + warp;      // target index within batch
    const int src = m * 4;                    // STRIDE = 4

    const float tx = sp[src * 3 + 0];
    const float ty = sp[src * 3 + 1];
    const float tz = sp[src * 3 + 2];

    // small margin so FP boundary cases are collected; exact dn<=1 mask is
    // re-applied in tfn_kernel, so over-collection is harmless.
    const float TH = 0.16f * 1.00002f;

    int base = 0;
    for (int c = lane; c < N_; c += 32) {
        float dx = sp[c * 3 + 0] - tx;
        float dy = sp[c * 3 + 1] - ty;
        float dz = sp[c * 3 + 2] - tz;
        float d2 = dx * dx + dy * dy + dz * dz;
        bool p = (d2 <= TH);
        unsigned msk = __ballot_sync(0xffffffffu, p);
        if (p) {
            int pos = base + __popc(msk & ((1u << lane) - 1u));
            if (pos < 256) { sd2[warp][pos] = d2; sidx[warp][pos] = c; }
        }
        base += __popc(msk);
    }
    int cnt = min(base, 256);
    __syncwarp();

    int* out = g_nbr + (size_t)(b * M_ + m) * KNN_;
    if (cnt <= KNN_) {
        out[lane] = (lane < cnt) ? sidx[warp][lane] : -1;
    } else {
        // exact 32-smallest by rank (ties broken by index, matching stable top_k)
        for (int i = lane; i < cnt; i += 32) {
            float di = sd2[warp][i];
            int rank = 0;
            for (int jj = 0; jj < cnt; jj++) {
                float dj = sd2[warp][jj];
                rank += (dj < di) || (dj == di && jj < i);
            }
            if (rank < KNN_) out[rank] = sidx[warp][i];
        }
    }
}

// ---------------------------------------------------------------------------
// K2: A = feats @ Wbig.  (65536 x 64) @ (64 x 768), fp32 SIMT.
// 128x128 tile, BK=32, 8x8 register blocking, padded As -> conflict-free LDS.
// ---------------------------------------------------------------------------
#define BM 128
#define BN 128
#define BK 32

__global__ __launch_bounds__(256) void gemm_kernel(const float* __restrict__ feats)
{
    __shared__ float As[BM][BK + 1];   // [row][k], padded
    __shared__ float Bs[BK][BN];       // [k][col]

    const int r0 = blockIdx.x * BM;
    const int j0 = blockIdx.y * BN;
    const int tid = threadIdx.x;
    const int tr = tid >> 4;           // 0..15
    const int tc = tid & 15;           // 0..15

    float acc[8][8];
#pragma unroll
    for (int i = 0; i < 8; i++)
#pragma unroll
        for (int j = 0; j < 8; j++) acc[i][j] = 0.0f;

    for (int kt = 0; kt < C_; kt += BK) {
        __syncthreads();
        for (int idx = tid; idx < BM * BK; idx += 256) {
            int r = idx >> 5, k = idx & 31;
            As[r][k] = feats[(size_t)(r0 + r) * C_ + kt + k];
        }
        for (int idx = tid; idx < BK * BN; idx += 256) {
            int c = idx >> 7, j = idx & 127;
            Bs[c][j] = g_Wbig[(kt + c) * NJ_ + j0 + j];
        }
        __syncthreads();

#pragma unroll
        for (int k = 0; k < BK; k++) {
            float a[8], bb[8];
#pragma unroll
            for (int i = 0; i < 8; i++) a[i] = As[tr + 16 * i][k];
#pragma unroll
            for (int j = 0; j < 8; j++) bb[j] = Bs[k][tc + 16 * j];
#pragma unroll
            for (int i = 0; i < 8; i++)
#pragma unroll
                for (int j = 0; j < 8; j++) acc[i][j] += a[i] * bb[j];
        }
    }

#pragma unroll
    for (int i = 0; i < 8; i++) {
        size_t row = (size_t)(r0 + tr + 16 * i) * NJ_ + j0 + tc;
#pragma unroll
        for (int j = 0; j < 8; j++) g_A[row + 16 * j] = acc[i][j];
    }
}

// ---------------------------------------------------------------------------
// K3: per-target TFN: geometry (Y, shell weights, per-shell normalization),
// gather A rows, accumulate o[r,u] = sum_k Y[k,r] * (sum_s wn[k,s] A[nk,l,s,u]),
// slab-norm, sqrt, atomic max-pool into g_H.
// ---------------------------------------------------------------------------
__global__ __launch_bounds__(256) void tfn_kernel(const float* __restrict__ points,
                                                  const float* __restrict__ b0)
{
    __shared__ float Ysh[KNN_][16];
    __shared__ float wsh[KNN_][3];
    __shared__ int   nsh[KNN_];
    __shared__ int   fsh[KNN_];

    const int t = blockIdx.x;
    const int b = t >> 9;        // /512
    const int m = t & 511;
    const float* pb = points + (size_t)b * N_ * 3;

    if (threadIdx.x < 32) {
        const int k = threadIdx.x;
        const int nb = g_nbr[(size_t)t * KNN_ + k];
        nsh[k] = nb;
        float w0s = 0.f, w1s = 0.f, w2s = 0.f;
        float Y[16];
#pragma unroll
        for (int i = 0; i < 16; i++) Y[i] = 0.f;

        if (nb >= 0) {
            const int src = m * 4;
            float rx = pb[nb * 3 + 0] - pb[src * 3 + 0];
            float ry = pb[nb * 3 + 1] - pb[src * 3 + 1];
            float rz = pb[nb * 3 + 2] - pb[src * 3 + 2];
            float d2 = rx * rx + ry * ry + rz * rz;
            float dist = sqrtf(fmaxf(d2, 1e-12f));
            float inv = 1.0f / dist;
            float x = rx * inv, y = ry * inv, z = rz * inv;
            float x2 = x * x, y2 = y * y, z2 = z * z;
            Y[0]  = 0.282095f;
            Y[1]  = 0.488603f * y;
            Y[2]  = 0.488603f * z;
            Y[3]  = 0.488603f * x;
            Y[4]  = 1.092548f * x * y;
            Y[5]  = 1.092548f * y * z;
            Y[6]  = 0.315392f * (3.0f * z2 - 1.0f);
            Y[7]  = 1.092548f * x * z;
            Y[8]  = 0.546274f * (x2 - y2);
            Y[9]  = 0.590044f * y * (3.0f * x2 - y2);
            Y[10] = 2.890611f * x * y * z;
            Y[11] = 0.457046f * y * (5.0f * z2 - 1.0f);
            Y[12] = 0.373176f * z * (5.0f * z2 - 3.0f);
            Y[13] = 0.457046f * x * (5.0f * z2 - 1.0f);
            Y[14] = 1.445306f * z * (x2 - y2);
            Y[15] = 0.590044f * x * (x2 - 3.0f * y2);

            float dn = dist * 2.5f;     // dist / RADIUS
            if (dn <= 1.0f) {
                const float G = 6.2383246250f;   // ln2 * 9
                float d1 = dn - 0.5f;
                float dq = dn - 1.0f;
                w0s = expf(-G * dn * dn);
                w1s = expf(-G * d1 * d1);
                w2s = expf(-G * dq * dq);
            }
        }
#pragma unroll
        for (int i = 0; i < 16; i++) Ysh[k][i] = Y[i];

        // per-shell sums over the 32 neighbors (warp reduce)
        float s0 = w0s, s1 = w1s, s2 = w2s;
#pragma unroll
        for (int d = 16; d > 0; d >>= 1) {
            s0 += __shfl_xor_sync(0xffffffffu, s0, d);
            s1 += __shfl_xor_sync(0xffffffffu, s1, d);
            s2 += __shfl_xor_sync(0xffffffffu, s2, d);
        }
        wsh[k][0] = w0s / (s0 + 1e-8f);
        wsh[k][1] = w1s / (s1 + 1e-8f);
        wsh[k][2] = w2s / (s2 + 1e-8f);
        fsh[k] = ((w0s + w1s + w2s) > 0.0f) ? 1 : 0;
    }
    __syncthreads();

    const int j = threadIdx.x;
    const int l = j >> 6;
    const int u = j & 63;
    const int baser = l * l;          // {0,1,4,9}
    const int nr = 2 * l + 1;         // {1,3,5,7}

    float acc[7];
#pragma unroll
    for (int r = 0; r < 7; r++) acc[r] = 0.0f;

    const float* Ab = g_A + (size_t)b * N_ * NJ_ + l * 192 + u;
    for (int k = 0; k < KNN_; k++) {
        if (!fsh[k]) continue;        // uniform branch (smem value)
        const float* Ar = Ab + (size_t)nsh[k] * NJ_;
        float g = wsh[k][0] * Ar[0] + wsh[k][1] * Ar[64] + wsh[k][2] * Ar[128];
#pragma unroll
        for (int r = 0; r < 7; r++)
            if (r < nr) acc[r] += Ysh[k][baser + r] * g;
    }

    if (l == 0) acc[0] += b0[u];
    float ss = 0.0f;
#pragma unroll
    for (int r = 0; r < 7; r++)
        if (r < nr) ss += acc[r] * acc[r];
    float h = sqrtf(fmaxf(ss, 1e-8f));

    // max-pool over targets: h > 0 always, so int-compare == float-compare
    atomicMax((int*)&g_H[b * 256 + l * 64 + u], __float_as_int(h));
}

// ---------------------------------------------------------------------------
// K4: tiny MLP head + softmax, one block per batch element.
// ---------------------------------------------------------------------------
__global__ __launch_bounds__(256) void mlp_kernel(
    const float* __restrict__ Wfc1, const float* __restrict__ bfc1,
    const float* __restrict__ Wfc2, const float* __restrict__ bfc2,
    const float* __restrict__ Wsm,  const float* __restrict__ bsm,
    float* __restrict__ out)
{
    __shared__ float sH[256];
    __shared__ float s1[512];
    __shared__ float s2[256];
    __shared__ float sl[40];

    const int b = blockIdx.x;
    const int tidx = threadIdx.x;

    sH[tidx] = g_H[b * 256 + tidx];
    __syncthreads();

    for (int u = tidx; u < 512; u += 256) {
        float a = bfc1[u];
#pragma unroll 8
        for (int k = 0; k < 256; k++) a += sH[k] * Wfc1[k * 512 + u];
        s1[u] = fmaxf(a, 0.0f);
    }
    __syncthreads();

    {
        float a = bfc2[tidx];
#pragma unroll 8
        for (int k = 0; k < 512; k++) a += s1[k] * Wfc2[k * 256 + tidx];
        s2[tidx] = fmaxf(a, 0.0f);
    }
    __syncthreads();

    if (tidx < 40) {
        float a = bsm[tidx];
#pragma unroll 8
        for (int k = 0; k < 256; k++) a += s2[k] * Wsm[k * 40 + tidx];
        sl[tidx] = a;
    }
    __syncthreads();

    if (tidx == 0) {
        float mx = -1e30f;
        for (int i = 0; i < 40; i++) mx = fmaxf(mx, sl[i]);
        float s = 0.0f;
        for (int i = 0; i < 40; i++) { float e = expf(sl[i] - mx); sl[i] = e; s += e; }
        float invs = 1.0f / s;
        for (int i = 0; i < 40; i++) out[b * 40 + i] = sl[i] * invs;
    }
}

// ---------------------------------------------------------------------------
// launch
// ---------------------------------------------------------------------------
extern "C" void kernel_launch(void* const* d_in, const int* in_sizes, int n_in,
                              void* d_out, int out_size)
{
    const float* points = (const float*)d_in[0];
    const float* feats  = (const float*)d_in[1];
    const float* W0     = (const float*)d_in[2];
    const float* b0     = (const float*)d_in[3];
    const float* W1     = (const float*)d_in[4];
    const float* W2     = (const float*)d_in[5];
    const float* W3     = (const float*)d_in[6];
    const float* Wfc1   = (const float*)d_in[7];
    const float* bfc1   = (const float*)d_in[8];
    const float* Wfc2   = (const float*)d_in[9];
    const float* bfc2   = (const float*)d_in[10];
    const float* Wsm    = (const float*)d_in[11];
    const float* bsm    = (const float*)d_in[12];
    float* out = (float*)d_out;

    prep_kernel<<<192, 256>>>(W0, W1, W2, W3);
    knn_kernel<<<dim3(M_ / 8, B_), 256>>>(points);
    gemm_kernel<<<dim3(NPTS_ / BM, NJ_ / BN), 256>>>(feats);
    tfn_kernel<<<T_, 256>>>(points, b0);
    mlp_kernel<<<B_, 256>>>(Wfc1, bfc1, Wfc2, bfc2, Wsm, bsm, out);
}

// round 12
// speedup vs baseline: 1.0004x; 1.0004x over previous
#include <cuda_runtime.h>
#include <math.h>

// ---------------------------------------------------------------------------
// Problem constants
// ---------------------------------------------------------------------------
#define B_      32
#define N_      2048
#define M_      512            // N_/STRIDE
#define T_      (B_ * M_)      // 16384 targets
#define C_      64
#define KNN_    32
#define NJ_     768            // 4 slabs * 3 shells * 64 units
#define NPTS_   (B_ * N_)      // 65536

// Scratch (allowed: __device__ globals, no runtime allocation)
__device__ float g_A[(size_t)NPTS_ * NJ_];   // point-level transformed features
__device__ float g_Wbig[C_ * NJ_];           // repacked weights [c][(l,s,u)]
__device__ int   g_nbr[T_ * KNN_];           // neighbor indices, -1 padded
__device__ float g_H[B_ * 256];              // max-pooled features

// ---------------------------------------------------------------------------
// K0: repack W0..W3 -> Wbig[c][(l*3+s)*64+u] = W_l[(s*64+c)*64+u]; zero g_H
// ---------------------------------------------------------------------------
__global__ void prep_kernel(const float* __restrict__ W0, const float* __restrict__ W1,
                            const float* __restrict__ W2, const float* __restrict__ W3)
{
    int tid = blockIdx.x * blockDim.x + threadIdx.x;
    if (tid < B_ * 256) g_H[tid] = 0.0f;
    if (tid < C_ * NJ_) {
        int c = tid / NJ_;
        int j = tid - c * NJ_;
        int l = j / 192;
        int r = j - l * 192;
        int s = r >> 6;
        int u = r & 63;
        const float* W = (l == 0) ? W0 : (l == 1) ? W1 : (l == 2) ? W2 : W3;
        g_Wbig[tid] = W[(s * 64 + c) * 64 + u];
    }
}

// ---------------------------------------------------------------------------
// K1: KNN via radius filter + exact rank-select fallback.
// Correctness argument: neighbors with dist > RADIUS have weight exactly 0
// (mask dn<=1 in the reference), so when in-radius count <= 32 any top-32
// superset is equivalent; when count > 32 we exactly select the 32 smallest
// d2 (same as jax top_k on -d2).
// One warp per target; points of the batch staged in shared memory.
// ---------------------------------------------------------------------------
__global__ __launch_bounds__(256) void knn_kernel(const float* __restrict__ points)
{
    __shared__ float sp[N_ * 3];          // 24 KB
    __shared__ float sd2[8][256];         // 8 KB
    __shared__ int   sidx[8][256];        // 8 KB

    const int b = blockIdx.y;
    const float* pb = points + (size_t)b * N_ * 3;
    for (int i = threadIdx.x; i < N_ * 3; i += 256) sp[i] = pb[i];
    __syncthreads();

    const int warp = threadIdx.x >> 5;
    const int lane = threadIdx.x & 31;
    const int m = blockIdx.x * 8 + warp;      // target index within batch
    const int src = m * 4;                    // STRIDE = 4

    const float tx = sp[src * 3 + 0];
    const float ty = sp[src * 3 + 1];
    const float tz = sp[src * 3 + 2];

    // small margin so FP boundary cases are collected; exact dn<=1 mask is
    // re-applied in tfn_kernel, so over-collection is harmless.
    const float TH = 0.16f * 1.00002f;

    int base = 0;
    for (int c = lane; c < N_; c += 32) {
        float dx = sp[c * 3 + 0] - tx;
        float dy = sp[c * 3 + 1] - ty;
        float dz = sp[c * 3 + 2] - tz;
        float d2 = dx * dx + dy * dy + dz * dz;
        bool p = (d2 <= TH);
        unsigned msk = __ballot_sync(0xffffffffu, p);
        if (p) {
            int pos = base + __popc(msk & ((1u << lane) - 1u));
            if (pos < 256) { sd2[warp][pos] = d2; sidx[warp][pos] = c; }
        }
        base += __popc(msk);
    }
    int cnt = min(base, 256);
    __syncwarp();

    int* out = g_nbr + (size_t)(b * M_ + m) * KNN_;
    if (cnt <= KNN_) {
        out[lane] = (lane < cnt) ? sidx[warp][lane] : -1;
    } else {
        // exact 32-smallest by rank (ties broken by index, matching stable top_k)
        for (int i = lane; i < cnt; i += 32) {
            float di = sd2[warp][i];
            int rank = 0;
            for (int jj = 0; jj < cnt; jj++) {
                float dj = sd2[warp][jj];
                rank += (dj < di) || (dj == di && jj < i);
            }
            if (rank < KNN_) out[rank] = sidx[warp][i];
        }
    }
}

// ---------------------------------------------------------------------------
// K2: A = feats @ Wbig.  (65536 x 64) @ (64 x 768), fp32 SIMT.
// 128x128 tile, BK=32, 8x8 register blocking, padded As -> conflict-free LDS.
// ---------------------------------------------------------------------------
#define BM 128
#define BN 128
#define BK 32

__global__ __launch_bounds__(256) void gemm_kernel(const float* __restrict__ feats)
{
    __shared__ float As[BM][BK + 1];   // [row][k], padded
    __shared__ float Bs[BK][BN];       // [k][col]

    const int r0 = blockIdx.x * BM;
    const int j0 = blockIdx.y * BN;
    const int tid = threadIdx.x;
    const int tr = tid >> 4;           // 0..15
    const int tc = tid & 15;           // 0..15

    float acc[8][8];
#pragma unroll
    for (int i = 0; i < 8; i++)
#pragma unroll
        for (int j = 0; j < 8; j++) acc[i][j] = 0.0f;

    for (int kt = 0; kt < C_; kt += BK) {
        __syncthreads();
        for (int idx = tid; idx < BM * BK; idx += 256) {
            int r = idx >> 5, k = idx & 31;
            As[r][k] = feats[(size_t)(r0 + r) * C_ + kt + k];
        }
        for (int idx = tid; idx < BK * BN; idx += 256) {
            int c = idx >> 7, j = idx & 127;
            Bs[c][j] = g_Wbig[(kt + c) * NJ_ + j0 + j];
        }
        __syncthreads();

#pragma unroll
        for (int k = 0; k < BK; k++) {
            float a[8], bb[8];
#pragma unroll
            for (int i = 0; i < 8; i++) a[i] = As[tr + 16 * i][k];
#pragma unroll
            for (int j = 0; j < 8; j++) bb[j] = Bs[k][tc + 16 * j];
#pragma unroll
            for (int i = 0; i < 8; i++)
#pragma unroll
                for (int j = 0; j < 8; j++) acc[i][j] += a[i] * bb[j];
        }
    }

#pragma unroll
    for (int i = 0; i < 8; i++) {
        size_t row = (size_t)(r0 + tr + 16 * i) * NJ_ + j0 + tc;
#pragma unroll
        for (int j = 0; j < 8; j++) g_A[row + 16 * j] = acc[i][j];
    }
}

// ---------------------------------------------------------------------------
// K3: per-target TFN: geometry (Y, shell weights, per-shell normalization),
// gather A rows, accumulate o[r,u] = sum_k Y[k,r] * (sum_s wn[k,s] A[nk,l,s,u]),
// slab-norm, sqrt, atomic max-pool into g_H.
// ---------------------------------------------------------------------------
__global__ __launch_bounds__(256) void tfn_kernel(const float* __restrict__ points,
                                                  const float* __restrict__ b0)
{
    __shared__ float Ysh[KNN_][16];
    __shared__ float wsh[KNN_][3];
    __shared__ int   nsh[KNN_];
    __shared__ int   fsh[KNN_];

    const int t = blockIdx.x;
    const int b = t >> 9;        // /512
    const int m = t & 511;
    const float* pb = points + (size_t)b * N_ * 3;

    if (threadIdx.x < 32) {
        const int k = threadIdx.x;
        const int nb = g_nbr[(size_t)t * KNN_ + k];
        nsh[k] = nb;
        float w0s = 0.f, w1s = 0.f, w2s = 0.f;
        float Y[16];
#pragma unroll
        for (int i = 0; i < 16; i++) Y[i] = 0.f;

        if (nb >= 0) {
            const int src = m * 4;
            float rx = pb[nb * 3 + 0] - pb[src * 3 + 0];
            float ry = pb[nb * 3 + 1] - pb[src * 3 + 1];
            float rz = pb[nb * 3 + 2] - pb[src * 3 + 2];
            float d2 = rx * rx + ry * ry + rz * rz;
            float dist = sqrtf(fmaxf(d2, 1e-12f));
            float inv = 1.0f / dist;
            float x = rx * inv, y = ry * inv, z = rz * inv;
            float x2 = x * x, y2 = y * y, z2 = z * z;
            Y[0]  = 0.282095f;
            Y[1]  = 0.488603f * y;
            Y[2]  = 0.488603f * z;
            Y[3]  = 0.488603f * x;
            Y[4]  = 1.092548f * x * y;
            Y[5]  = 1.092548f * y * z;
            Y[6]  = 0.315392f * (3.0f * z2 - 1.0f);
            Y[7]  = 1.092548f * x * z;
            Y[8]  = 0.546274f * (x2 - y2);
            Y[9]  = 0.590044f * y * (3.0f * x2 - y2);
            Y[10] = 2.890611f * x * y * z;
            Y[11] = 0.457046f * y * (5.0f * z2 - 1.0f);
            Y[12] = 0.373176f * z * (5.0f * z2 - 3.0f);
            Y[13] = 0.457046f * x * (5.0f * z2 - 1.0f);
            Y[14] = 1.445306f * z * (x2 - y2);
            Y[15] = 0.590044f * x * (x2 - 3.0f * y2);

            float dn = dist * 2.5f;     // dist / RADIUS
            if (dn <= 1.0f) {
                const float G = 6.2383246250f;   // ln2 * 9
                float d1 = dn - 0.5f;
                float dq = dn - 1.0f;
                w0s = expf(-G * dn * dn);
                w1s = expf(-G * d1 * d1);
                w2s = expf(-G * dq * dq);
            }
        }
#pragma unroll
        for (int i = 0; i < 16; i++) Ysh[k][i] = Y[i];

        // per-shell sums over the 32 neighbors (warp reduce)
        float s0 = w0s, s1 = w1s, s2 = w2s;
#pragma unroll
        for (int d = 16; d > 0; d >>= 1) {
            s0 += __shfl_xor_sync(0xffffffffu, s0, d);
            s1 += __shfl_xor_sync(0xffffffffu, s1, d);
            s2 += __shfl_xor_sync(0xffffffffu, s2, d);
        }
        wsh[k][0] = w0s / (s0 + 1e-8f);
        wsh[k][1] = w1s / (s1 + 1e-8f);
        wsh[k][2] = w2s / (s2 + 1e-8f);
        fsh[k] = ((w0s + w1s + w2s) > 0.0f) ? 1 : 0;
    }
    __syncthreads();

    const int j = threadIdx.x;
    const int l = j >> 6;
    const int u = j & 63;
    const int baser = l * l;          // {0,1,4,9}
    const int nr = 2 * l + 1;         // {1,3,5,7}

    float acc[7];
#pragma unroll
    for (int r = 0; r < 7; r++) acc[r] = 0.0f;

    const float* Ab = g_A + (size_t)b * N_ * NJ_ + l * 192 + u;
    for (int k = 0; k < KNN_; k++) {
        if (!fsh[k]) continue;        // uniform branch (smem value)
        const float* Ar = Ab + (size_t)nsh[k] * NJ_;
        float g = wsh[k][0] * Ar[0] + wsh[k][1] * Ar[64] + wsh[k][2] * Ar[128];
#pragma unroll
        for (int r = 0; r < 7; r++)
            if (r < nr) acc[r] += Ysh[k][baser + r] * g;
    }

    if (l == 0) acc[0] += b0[u];
    float ss = 0.0f;
#pragma unroll
    for (int r = 0; r < 7; r++)
        if (r < nr) ss += acc[r] * acc[r];
    float h = sqrtf(fmaxf(ss, 1e-8f));

    // max-pool over targets: h > 0 always, so int-compare == float-compare
    atomicMax((int*)&g_H[b * 256 + l * 64 + u], __float_as_int(h));
}

// ---------------------------------------------------------------------------
// K4: tiny MLP head + softmax, one block per batch element.
// ---------------------------------------------------------------------------
__global__ __launch_bounds__(256) void mlp_kernel(
    const float* __restrict__ Wfc1, const float* __restrict__ bfc1,
    const float* __restrict__ Wfc2, const float* __restrict__ bfc2,
    const float* __restrict__ Wsm,  const float* __restrict__ bsm,
    float* __restrict__ out)
{
    __shared__ float sH[256];
    __shared__ float s1[512];
    __shared__ float s2[256];
    __shared__ float sl[40];

    const int b = blockIdx.x;
    const int tidx = threadIdx.x;

    sH[tidx] = g_H[b * 256 + tidx];
    __syncthreads();

    for (int u = tidx; u < 512; u += 256) {
        float a = bfc1[u];
#pragma unroll 8
        for (int k = 0; k < 256; k++) a += sH[k] * Wfc1[k * 512 + u];
        s1[u] = fmaxf(a, 0.0f);
    }
    __syncthreads();

    {
        float a = bfc2[tidx];
#pragma unroll 8
        for (int k = 0; k < 512; k++) a += s1[k] * Wfc2[k * 256 + tidx];
        s2[tidx] = fmaxf(a, 0.0f);
    }
    __syncthreads();

    if (tidx < 40) {
        float a = bsm[tidx];
#pragma unroll 8
        for (int k = 0; k < 256; k++) a += s2[k] * Wsm[k * 40 + tidx];
        sl[tidx] = a;
    }
    __syncthreads();

    if (tidx == 0) {
        float mx = -1e30f;
        for (int i = 0; i < 40; i++) mx = fmaxf(mx, sl[i]);
        float s = 0.0f;
        for (int i = 0; i < 40; i++) { float e = expf(sl[i] - mx); sl[i] = e; s += e; }
        float invs = 1.0f / s;
        for (int i = 0; i < 40; i++) out[b * 40 + i] = sl[i] * invs;
    }
}

// ---------------------------------------------------------------------------
// launch
// ---------------------------------------------------------------------------
extern "C" void kernel_launch(void* const* d_in, const int* in_sizes, int n_in,
                              void* d_out, int out_size)
{
    const float* points = (const float*)d_in[0];
    const float* feats  = (const float*)d_in[1];
    const float* W0     = (const float*)d_in[2];
    const float* b0     = (const float*)d_in[3];
    const float* W1     = (const float*)d_in[4];
    const float* W2     = (const float*)d_in[5];
    const float* W3     = (const float*)d_in[6];
    const float* Wfc1   = (const float*)d_in[7];
    const float* bfc1   = (const float*)d_in[8];
    const float* Wfc2   = (const float*)d_in[9];
    const float* bfc2   = (const float*)d_in[10];
    const float* Wsm    = (const float*)d_in[11];
    const float* bsm    = (const float*)d_in[12];
    float* out = (float*)d_out;

    prep_kernel<<<192, 256>>>(W0, W1, W2, W3);
    knn_kernel<<<dim3(M_ / 8, B_), 256>>>(points);
    gemm_kernel<<<dim3(NPTS_ / BM, NJ_ / BN), 256>>>(feats);
    tfn_kernel<<<T_, 256>>>(points, b0);
    mlp_kernel<<<B_, 256>>>(Wfc1, bfc1, Wfc2, bfc2, Wsm, bsm, out);
}

// round 13
// speedup vs baseline: 1.2211x; 1.2207x over previous
#include <cuda_runtime.h>
#include <math.h>
#include <stdint.h>

// ---------------------------------------------------------------------------
// Problem constants
// ---------------------------------------------------------------------------
#define B_      32
#define N_      2048
#define M_      512            // N_/STRIDE
#define T_      (B_ * M_)      // 16384 targets
#define C_      64
#define KNN_    32
#define NJ_     768            // 4 slabs * 3 shells * 64 units
#define NPTS_   (B_ * N_)      // 65536

// Scratch (allowed: __device__ globals, no runtime allocation)
__device__ float g_A[(size_t)NPTS_ * NJ_];   // point-level transformed features
__device__ float g_Wbig[C_ * NJ_];           // repacked weights [c][(l,s,u)]
__device__ int   g_nbr[T_ * KNN_];           // neighbor indices, -1 padded
__device__ float g_H[B_ * 256];              // max-pooled features

// ---------------------------------------------------------------------------
// K0: repack W0..W3 -> Wbig[c][(l*3+s)*64+u] = W_l[(s*64+c)*64+u]; zero g_H
// ---------------------------------------------------------------------------
__global__ void prep_kernel(const float* __restrict__ W0, const float* __restrict__ W1,
                            const float* __restrict__ W2, const float* __restrict__ W3)
{
    int tid = blockIdx.x * blockDim.x + threadIdx.x;
    if (tid < B_ * 256) g_H[tid] = 0.0f;
    if (tid < C_ * NJ_) {
        int c = tid / NJ_;
        int j = tid - c * NJ_;
        int l = j / 192;
        int r = j - l * 192;
        int s = r >> 6;
        int u = r & 63;
        const float* W = (l == 0) ? W0 : (l == 1) ? W1 : (l == 2) ? W2 : W3;
        g_Wbig[tid] = W[(s * 64 + c) * 64 + u];
    }
}

// ---------------------------------------------------------------------------
// K1: KNN via radius filter + exact rank-select fallback (unchanged; correct).
// ---------------------------------------------------------------------------
__global__ __launch_bounds__(256) void knn_kernel(const float* __restrict__ points)
{
    __shared__ float sp[N_ * 3];
    __shared__ float sd2[8][256];
    __shared__ int   sidx[8][256];

    const int b = blockIdx.y;
    const float* pb = points + (size_t)b * N_ * 3;
    for (int i = threadIdx.x; i < N_ * 3; i += 256) sp[i] = pb[i];
    __syncthreads();

    const int warp = threadIdx.x >> 5;
    const int lane = threadIdx.x & 31;
    const int m = blockIdx.x * 8 + warp;
    const int src = m * 4;

    const float tx = sp[src * 3 + 0];
    const float ty = sp[src * 3 + 1];
    const float tz = sp[src * 3 + 2];

    const float TH = 0.16f * 1.00002f;

    int base = 0;
    for (int c = lane; c < N_; c += 32) {
        float dx = sp[c * 3 + 0] - tx;
        float dy = sp[c * 3 + 1] - ty;
        float dz = sp[c * 3 + 2] - tz;
        float d2 = dx * dx + dy * dy + dz * dz;
        bool p = (d2 <= TH);
        unsigned msk = __ballot_sync(0xffffffffu, p);
        if (p) {
            int pos = base + __popc(msk & ((1u << lane) - 1u));
            if (pos < 256) { sd2[warp][pos] = d2; sidx[warp][pos] = c; }
        }
        base += __popc(msk);
    }
    int cnt = min(base, 256);
    __syncwarp();

    int* out = g_nbr + (size_t)(b * M_ + m) * KNN_;
    if (cnt <= KNN_) {
        out[lane] = (lane < cnt) ? sidx[warp][lane] : -1;
    } else {
        for (int i = lane; i < cnt; i += 32) {
            float di = sd2[warp][i];
            int rank = 0;
            for (int jj = 0; jj < cnt; jj++) {
                float dj = sd2[warp][jj];
                rank += (dj < di) || (dj == di && jj < i);
            }
            if (rank < KNN_) out[rank] = sidx[warp][i];
        }
    }
}

// ---------------------------------------------------------------------------
// K2: A = feats @ Wbig via mma.sync tf32 with 3xTF32 split (fp32-accurate).
// Block tile 128x128, K=64 in two 32-wide smem tiles. 8 warps (4 M x 2 N),
// warp tile 32x64 = 2x8 m16n8k8 fragments. 3 mma passes per fragment:
// hi*hi + lo*hi + hi*lo (error ~2^-22).
// ---------------------------------------------------------------------------
#define GBM 128
#define GBN 128
#define GBK 32

__device__ __forceinline__ void split_tf32(float x, uint32_t& hi, uint32_t& lo)
{
    uint32_t h;
    asm("cvt.rna.tf32.f32 %0, %1;" : "=r"(h) : "f"(x));
    hi = h;
    lo = __float_as_uint(x - __uint_as_float(h));
}

__device__ __forceinline__ void mma_tf32(float* d, const uint32_t* a, const uint32_t* b)
{
    asm volatile(
        "mma.sync.aligned.m16n8k8.row.col.f32.tf32.tf32.f32 "
        "{%0,%1,%2,%3},{%4,%5,%6,%7},{%8,%9},{%0,%1,%2,%3};\n"
        : "+f"(d[0]), "+f"(d[1]), "+f"(d[2]), "+f"(d[3])
        : "r"(a[0]), "r"(a[1]), "r"(a[2]), "r"(a[3]), "r"(b[0]), "r"(b[1]));
}

__global__ __launch_bounds__(256) void gemm_tc_kernel(const float* __restrict__ feats)
{
    __shared__ float As[GBM][GBK + 4];   // stride 36 -> (4r+k)%32 conflict-free
    __shared__ float Bs[GBK][GBN + 8];   // stride 136 -> (8k+n)%32 conflict-free

    const int tid  = threadIdx.x;
    const int warp = tid >> 5;
    const int lane = tid & 31;
    const int wm   = warp & 3;     // 0..3 (M)
    const int wn   = warp >> 2;    // 0..1 (N)
    const int r0   = blockIdx.x * GBM;
    const int j0   = blockIdx.y * GBN;

    float acc[2][8][4];
#pragma unroll
    for (int mt = 0; mt < 2; mt++)
#pragma unroll
        for (int nt = 0; nt < 8; nt++)
#pragma unroll
            for (int i = 0; i < 4; i++) acc[mt][nt][i] = 0.0f;

    for (int kt = 0; kt < C_; kt += GBK) {
        __syncthreads();
#pragma unroll
        for (int it = 0; it < 4; it++) {
            int idx = tid + it * 256;            // 0..1023
            int r  = idx >> 3;                   // 8 float4 per A row
            int c4 = idx & 7;
            float4 v = *(const float4*)(feats + (size_t)(r0 + r) * C_ + kt + c4 * 4);
            *(float4*)(&As[r][c4 * 4]) = v;
        }
#pragma unroll
        for (int it = 0; it < 4; it++) {
            int idx = tid + it * 256;
            int r  = idx >> 5;                   // 32 float4 per B row
            int c4 = idx & 31;
            float4 v = *(const float4*)(g_Wbig + (size_t)(kt + r) * NJ_ + j0 + c4 * 4);
            *(float4*)(&Bs[r][c4 * 4]) = v;
        }
        __syncthreads();

#pragma unroll
        for (int ks = 0; ks < GBK; ks += 8) {
            uint32_t ahi[2][4], alo[2][4];
#pragma unroll
            for (int mt = 0; mt < 2; mt++) {
                int row = wm * 32 + mt * 16 + (lane >> 2);
                int col = ks + (lane & 3);
                split_tf32(As[row][col],         ahi[mt][0], alo[mt][0]);
                split_tf32(As[row + 8][col],     ahi[mt][1], alo[mt][1]);
                split_tf32(As[row][col + 4],     ahi[mt][2], alo[mt][2]);
                split_tf32(As[row + 8][col + 4], ahi[mt][3], alo[mt][3]);
            }
            uint32_t bhi[8][2], blo[8][2];
#pragma unroll
            for (int nt = 0; nt < 8; nt++) {
                int cn = wn * 64 + nt * 8 + (lane >> 2);
                int rk = ks + (lane & 3);
                split_tf32(Bs[rk][cn],     bhi[nt][0], blo[nt][0]);
                split_tf32(Bs[rk + 4][cn], bhi[nt][1], blo[nt][1]);
            }
#pragma unroll
            for (int mt = 0; mt < 2; mt++)
#pragma unroll
                for (int nt = 0; nt < 8; nt++) {
                    mma_tf32(acc[mt][nt], ahi[mt], bhi[nt]);
                    mma_tf32(acc[mt][nt], alo[mt], bhi[nt]);
                    mma_tf32(acc[mt][nt], ahi[mt], blo[nt]);
                }
        }
    }

    // Epilogue: fragment (c0,c1)=(row, 2c..2c+1), (c2,c3)=(row+8, same cols)
#pragma unroll
    for (int mt = 0; mt < 2; mt++) {
        int row = r0 + wm * 32 + mt * 16 + (lane >> 2);
#pragma unroll
        for (int nt = 0; nt < 8; nt++) {
            int col = j0 + wn * 64 + nt * 8 + 2 * (lane & 3);
            float2 v0 = make_float2(acc[mt][nt][0], acc[mt][nt][1]);
            float2 v1 = make_float2(acc[mt][nt][2], acc[mt][nt][3]);
            *(float2*)(g_A + (size_t)row * NJ_ + col)       = v0;
            *(float2*)(g_A + (size_t)(row + 8) * NJ_ + col) = v1;
        }
    }
}

// ---------------------------------------------------------------------------
// K3: per-target TFN, restructured:
//   * 4 targets per block (all in same batch: 4 | 512)
//   * active-neighbor compaction (ballot prefix) -> dense loop, batched loads
//   * float4 A loads (4 units/thread): 4x fewer LDG + smem reads per unit
//   * block-local max over the 4 targets -> 1/4 the atomics
// ---------------------------------------------------------------------------
__global__ __launch_bounds__(256) void tfn_kernel(const float* __restrict__ points,
                                                  const float* __restrict__ b0)
{
    __shared__ float cY[4][32][16];
    __shared__ float cW[4][32][3];
    __shared__ int   cOff[4][32];
    __shared__ int   cCnt[4];
    __shared__ float hbuf[4][64][4];

    const int tid  = threadIdx.x;
    const int warp = tid >> 5;
    const int lane = tid & 31;
    const int tBase = blockIdx.x * 4;
    const int bb = tBase >> 9;     // batch (same for all 4 targets)

    // ---- Phase 1: geometry + compaction (warps 0..3, one target each) ----
    if (warp < 4) {
        const int t = tBase + warp;
        const int m = t & 511;
        const float* pb = points + (size_t)bb * N_ * 3;
        const int nb = g_nbr[(size_t)t * KNN_ + lane];

        float w0s = 0.f, w1s = 0.f, w2s = 0.f;
        float Y[16];
#pragma unroll
        for (int i = 0; i < 16; i++) Y[i] = 0.f;

        if (nb >= 0) {
            const int src = m * 4;
            float rx = pb[nb * 3 + 0] - pb[src * 3 + 0];
            float ry = pb[nb * 3 + 1] - pb[src * 3 + 1];
            float rz = pb[nb * 3 + 2] - pb[src * 3 + 2];
            float d2 = rx * rx + ry * ry + rz * rz;
            float dist = sqrtf(fmaxf(d2, 1e-12f));
            float inv = 1.0f / dist;
            float x = rx * inv, y = ry * inv, z = rz * inv;
            float x2 = x * x, y2 = y * y, z2 = z * z;
            Y[0]  = 0.282095f;
            Y[1]  = 0.488603f * y;
            Y[2]  = 0.488603f * z;
            Y[3]  = 0.488603f * x;
            Y[4]  = 1.092548f * x * y;
            Y[5]  = 1.092548f * y * z;
            Y[6]  = 0.315392f * (3.0f * z2 - 1.0f);
            Y[7]  = 1.092548f * x * z;
            Y[8]  = 0.546274f * (x2 - y2);
            Y[9]  = 0.590044f * y * (3.0f * x2 - y2);
            Y[10] = 2.890611f * x * y * z;
            Y[11] = 0.457046f * y * (5.0f * z2 - 1.0f);
            Y[12] = 0.373176f * z * (5.0f * z2 - 3.0f);
            Y[13] = 0.457046f * x * (5.0f * z2 - 1.0f);
            Y[14] = 1.445306f * z * (x2 - y2);
            Y[15] = 0.590044f * x * (x2 - 3.0f * y2);

            float dn = dist * 2.5f;            // dist / RADIUS
            if (dn <= 1.0f) {
                const float G = 6.2383246250f; // ln2 * 9
                float d1 = dn - 0.5f;
                float dq = dn - 1.0f;
                w0s = expf(-G * dn * dn);
                w1s = expf(-G * d1 * d1);
                w2s = expf(-G * dq * dq);
            }
        }

        // per-shell sums over all 32 candidates (matches reference normalization)
        float s0 = w0s, s1 = w1s, s2 = w2s;
#pragma unroll
        for (int d = 16; d > 0; d >>= 1) {
            s0 += __shfl_xor_sync(0xffffffffu, s0, d);
            s1 += __shfl_xor_sync(0xffffffffu, s1, d);
            s2 += __shfl_xor_sync(0xffffffffu, s2, d);
        }

        bool act = (w0s + w1s + w2s) > 0.0f;   // dn<=1 && nb>=0
        unsigned msk = __ballot_sync(0xffffffffu, act);
        int pos = __popc(msk & ((1u << lane) - 1u));
        if (act) {
            cOff[warp][pos] = (bb * N_ + nb) * NJ_;
            cW[warp][pos][0] = w0s / (s0 + 1e-8f);
            cW[warp][pos][1] = w1s / (s1 + 1e-8f);
            cW[warp][pos][2] = w2s / (s2 + 1e-8f);
#pragma unroll
            for (int i = 0; i < 16; i++) cY[warp][pos][i] = Y[i];
        }
        if (lane == 0) cCnt[warp] = __popc(msk);
    }
    __syncthreads();

    // ---- Phase 2: accumulation. tg uniform per pair of warps. ----
    const int tg = tid >> 6;          // target within block
    const int j  = tid & 63;
    const int l  = j >> 4;            // slab
    const int u0 = (j & 15) << 2;     // 4 units per thread
    const int baser = l * l;
    const int nr = 2 * l + 1;
    const int cnt = cCnt[tg];

    float ax[7], ay[7], az[7], aw[7];
#pragma unroll
    for (int r = 0; r < 7; r++) { ax[r] = 0.f; ay[r] = 0.f; az[r] = 0.f; aw[r] = 0.f; }

    const float* Abase = g_A + l * 192 + u0;
#pragma unroll 2
    for (int k = 0; k < cnt; k++) {
        const float* Ar = Abase + cOff[tg][k];
        float4 A0 = *(const float4*)(Ar);
        float4 A1 = *(const float4*)(Ar + 64);
        float4 A2 = *(const float4*)(Ar + 128);
        float w0 = cW[tg][k][0], w1 = cW[tg][k][1], w2 = cW[tg][k][2];
        float gx = w0 * A0.x + w1 * A1.x + w2 * A2.x;
        float gy = w0 * A0.y + w1 * A1.y + w2 * A2.y;
        float gz = w0 * A0.z + w1 * A1.z + w2 * A2.z;
        float gw = w0 * A0.w + w1 * A1.w + w2 * A2.w;
        const float* Yk = &cY[tg][k][baser];
#pragma unroll
        for (int r = 0; r < 7; r++)
            if (r < nr) {
                float y = Yk[r];
                ax[r] += y * gx; ay[r] += y * gy;
                az[r] += y * gz; aw[r] += y * gw;
            }
    }

    if (l == 0) {
        ax[0] += b0[u0 + 0]; ay[0] += b0[u0 + 1];
        az[0] += b0[u0 + 2]; aw[0] += b0[u0 + 3];
    }

    float sx = 0.f, sy = 0.f, sz = 0.f, sw = 0.f;
#pragma unroll
    for (int r = 0; r < 7; r++)
        if (r < nr) {
            sx += ax[r] * ax[r]; sy += ay[r] * ay[r];
            sz += az[r] * az[r]; sw += aw[r] * aw[r];
        }
    hbuf[tg][j][0] = sqrtf(fmaxf(sx, 1e-8f));
    hbuf[tg][j][1] = sqrtf(fmaxf(sy, 1e-8f));
    hbuf[tg][j][2] = sqrtf(fmaxf(sz, 1e-8f));
    hbuf[tg][j][3] = sqrtf(fmaxf(sw, 1e-8f));
    __syncthreads();

    // ---- Phase 3: block-local max over 4 targets, then one atomic ----
    {
        int jj = tid >> 2;            // 0..63
        int cc = tid & 3;             // 0..3
        float h = fmaxf(fmaxf(hbuf[0][jj][cc], hbuf[1][jj][cc]),
                        fmaxf(hbuf[2][jj][cc], hbuf[3][jj][cc]));
        int ll = jj >> 4;
        int uu = ((jj & 15) << 2) + cc;
        // h > 0 always, so int-compare == float-compare
        atomicMax((int*)&g_H[bb * 256 + ll * 64 + uu], __float_as_int(h));
    }
}

// ---------------------------------------------------------------------------
// K4: tiny MLP head + softmax, one block per batch element.
// ---------------------------------------------------------------------------
__global__ __launch_bounds__(256) void mlp_kernel(
    const float* __restrict__ Wfc1, const float* __restrict__ bfc1,
    const float* __restrict__ Wfc2, const float* __restrict__ bfc2,
    const float* __restrict__ Wsm,  const float* __restrict__ bsm,
    float* __restrict__ out)
{
    __shared__ float sH[256];
    __shared__ float s1[512];
    __shared__ float s2[256];
    __shared__ float sl[40];

    const int b = blockIdx.x;
    const int tidx = threadIdx.x;

    sH[tidx] = g_H[b * 256 + tidx];
    __syncthreads();

    for (int u = tidx; u < 512; u += 256) {
        float a = bfc1[u];
#pragma unroll 8
        for (int k = 0; k < 256; k++) a += sH[k] * Wfc1[k * 512 + u];
        s1[u] = fmaxf(a, 0.0f);
    }
    __syncthreads();

    {
        float a = bfc2[tidx];
#pragma unroll 8
        for (int k = 0; k < 512; k++) a += s1[k] * Wfc2[k * 256 + tidx];
        s2[tidx] = fmaxf(a, 0.0f);
    }
    __syncthreads();

    if (tidx < 40) {
        float a = bsm[tidx];
#pragma unroll 8
        for (int k = 0; k < 256; k++) a += s2[k] * Wsm[k * 40 + tidx];
        sl[tidx] = a;
    }
    __syncthreads();

    if (tidx == 0) {
        float mx = -1e30f;
        for (int i = 0; i < 40; i++) mx = fmaxf(mx, sl[i]);
        float s = 0.0f;
        for (int i = 0; i < 40; i++) { float e = expf(sl[i] - mx); sl[i] = e; s += e; }
        float invs = 1.0f / s;
        for (int i = 0; i < 40; i++) out[b * 40 + i] = sl[i] * invs;
    }
}

// ---------------------------------------------------------------------------
// launch
// ---------------------------------------------------------------------------
extern "C" void kernel_launch(void* const* d_in, const int* in_sizes, int n_in,
                              void* d_out, int out_size)
{
    const float* points = (const float*)d_in[0];
    const float* feats  = (const float*)d_in[1];
    const float* W0     = (const float*)d_in[2];
    const float* b0     = (const float*)d_in[3];
    const float* W1     = (const float*)d_in[4];
    const float* W2     = (const float*)d_in[5];
    const float* W3     = (const float*)d_in[6];
    const float* Wfc1   = (const float*)d_in[7];
    const float* bfc1   = (const float*)d_in[8];
    const float* Wfc2   = (const float*)d_in[9];
    const float* bfc2   = (const float*)d_in[10];
    const float* Wsm    = (const float*)d_in[11];
    const float* bsm    = (const float*)d_in[12];
    float* out = (float*)d_out;

    prep_kernel<<<192, 256>>>(W0, W1, W2, W3);
    knn_kernel<<<dim3(M_ / 8, B_), 256>>>(points);
    gemm_tc_kernel<<<dim3(NPTS_ / GBM, NJ_ / GBN), 256>>>(feats);
    tfn_kernel<<<T_ / 4, 256>>>(points, b0);
    mlp_kernel<<<B_, 256>>>(Wfc1, bfc1, Wfc2, bfc2, Wsm, bsm, out);
}

// round 14
// speedup vs baseline: 1.5391x; 1.2604x over previous
#include <cuda_runtime.h>
#include <math.h>
#include <stdint.h>

// ---------------------------------------------------------------------------
// Problem constants
// ---------------------------------------------------------------------------
#define B_      32
#define N_      2048
#define M_      512            // N_/STRIDE
#define T_      (B_ * M_)      // 16384 targets
#define C_      64
#define KNN_    32
#define NJ_     768            // 4 slabs * 3 shells * 64 units
#define NPTS_   (B_ * N_)      // 65536

// Scratch (allowed: __device__ globals, no runtime allocation)
__device__ float    g_A[(size_t)NPTS_ * NJ_];   // point-level transformed features
__device__ uint32_t g_Whi[C_ * NJ_];            // repacked weights, tf32 hi part
__device__ uint32_t g_Wlo[C_ * NJ_];            // fp32 residual (lo) part
__device__ int      g_nbr[T_ * KNN_];           // neighbor indices, -1 padded
__device__ float    g_H[B_ * 256];              // max-pooled features

// ---------------------------------------------------------------------------
// K0: repack W0..W3 -> Wbig[c][(l*3+s)*64+u] = W_l[(s*64+c)*64+u], pre-split
// into tf32 hi + fp32 residual lo. Also zero g_H.
// ---------------------------------------------------------------------------
__global__ void prep_kernel(const float* __restrict__ W0, const float* __restrict__ W1,
                            const float* __restrict__ W2, const float* __restrict__ W3)
{
    int tid = blockIdx.x * blockDim.x + threadIdx.x;
    if (tid < B_ * 256) g_H[tid] = 0.0f;
    if (tid < C_ * NJ_) {
        int c = tid / NJ_;
        int j = tid - c * NJ_;
        int l = j / 192;
        int r = j - l * 192;
        int s = r >> 6;
        int u = r & 63;
        const float* W = (l == 0) ? W0 : (l == 1) ? W1 : (l == 2) ? W2 : W3;
        float w = W[(s * 64 + c) * 64 + u];
        uint32_t hi;
        asm("cvt.rna.tf32.f32 %0, %1;" : "=r"(hi) : "f"(w));
        g_Whi[tid] = hi;
        g_Wlo[tid] = __float_as_uint(w - __uint_as_float(hi));
    }
}

// ---------------------------------------------------------------------------
// K1: KNN via radius filter + exact rank-select fallback (unchanged; correct).
// ---------------------------------------------------------------------------
__global__ __launch_bounds__(256) void knn_kernel(const float* __restrict__ points)
{
    __shared__ float sp[N_ * 3];
    __shared__ float sd2[8][256];
    __shared__ int   sidx[8][256];

    const int b = blockIdx.y;
    const float* pb = points + (size_t)b * N_ * 3;
    for (int i = threadIdx.x; i < N_ * 3; i += 256) sp[i] = pb[i];
    __syncthreads();

    const int warp = threadIdx.x >> 5;
    const int lane = threadIdx.x & 31;
    const int m = blockIdx.x * 8 + warp;
    const int src = m * 4;

    const float tx = sp[src * 3 + 0];
    const float ty = sp[src * 3 + 1];
    const float tz = sp[src * 3 + 2];

    const float TH = 0.16f * 1.00002f;

    int base = 0;
    for (int c = lane; c < N_; c += 32) {
        float dx = sp[c * 3 + 0] - tx;
        float dy = sp[c * 3 + 1] - ty;
        float dz = sp[c * 3 + 2] - tz;
        float d2 = dx * dx + dy * dy + dz * dz;
        bool p = (d2 <= TH);
        unsigned msk = __ballot_sync(0xffffffffu, p);
        if (p) {
            int pos = base + __popc(msk & ((1u << lane) - 1u));
            if (pos < 256) { sd2[warp][pos] = d2; sidx[warp][pos] = c; }
        }
        base += __popc(msk);
    }
    int cnt = min(base, 256);
    __syncwarp();

    int* out = g_nbr + (size_t)(b * M_ + m) * KNN_;
    if (cnt <= KNN_) {
        out[lane] = (lane < cnt) ? sidx[warp][lane] : -1;
    } else {
        for (int i = lane; i < cnt; i += 32) {
            float di = sd2[warp][i];
            int rank = 0;
            for (int jj = 0; jj < cnt; jj++) {
                float dj = sd2[warp][jj];
                rank += (dj < di) || (dj == di && jj < i);
            }
            if (rank < KNN_) out[rank] = sidx[warp][i];
        }
    }
}

// ---------------------------------------------------------------------------
// K2: A = feats @ Wbig via mma.sync tf32, 3xTF32 (fp32-accurate).
// Splits hoisted OUT of the inner loop: B pre-split in prep (global hi/lo),
// A split once per tile at smem fill. Inner loop = pure conflict-free LDS + mma.
// 71.7 KB dynamic smem.
// ---------------------------------------------------------------------------
#define GBM 128
#define GBN 128
#define GBK 32

#define ASTR 36    // (4r+c) mod 32 distinct  -> conflict-free frag loads
#define BSTR 136   // (8k+n) mod 32 distinct  -> conflict-free frag loads

__device__ __forceinline__ void mma_tf32(float* d, const uint32_t* a, const uint32_t* b)
{
    asm volatile(
        "mma.sync.aligned.m16n8k8.row.col.f32.tf32.tf32.f32 "
        "{%0,%1,%2,%3},{%4,%5,%6,%7},{%8,%9},{%0,%1,%2,%3};\n"
        : "+f"(d[0]), "+f"(d[1]), "+f"(d[2]), "+f"(d[3])
        : "r"(a[0]), "r"(a[1]), "r"(a[2]), "r"(a[3]), "r"(b[0]), "r"(b[1]));
}

__global__ __launch_bounds__(256) void gemm_tc_kernel(const float* __restrict__ feats)
{
    extern __shared__ uint32_t smem_g[];
    uint32_t* Ahi = smem_g;                        // [GBM][ASTR]
    uint32_t* Alo = Ahi + GBM * ASTR;              // [GBM][ASTR]
    uint32_t* Bhi = Alo + GBM * ASTR;              // [GBK][BSTR]
    uint32_t* Blo = Bhi + GBK * BSTR;              // [GBK][BSTR]

    const int tid  = threadIdx.x;
    const int warp = tid >> 5;
    const int lane = tid & 31;
    const int wm   = warp & 3;     // 0..3 (M)
    const int wn   = warp >> 2;    // 0..1 (N)
    const int r0   = blockIdx.x * GBM;
    const int j0   = blockIdx.y * GBN;

    float acc[2][8][4];
#pragma unroll
    for (int mt = 0; mt < 2; mt++)
#pragma unroll
        for (int nt = 0; nt < 8; nt++)
#pragma unroll
            for (int i = 0; i < 4; i++) acc[mt][nt][i] = 0.0f;

    for (int kt = 0; kt < C_; kt += GBK) {
        __syncthreads();
        // ---- A fill: load float4, split once, store hi/lo as uint4 ----
#pragma unroll
        for (int it = 0; it < 4; it++) {
            int idx = tid + it * 256;            // 0..1023
            int r  = idx >> 3;                   // 8 float4 per A row
            int c4 = idx & 7;
            float4 v = *(const float4*)(feats + (size_t)(r0 + r) * C_ + kt + c4 * 4);
            uint4 hi, lo;
            asm("cvt.rna.tf32.f32 %0, %1;" : "=r"(hi.x) : "f"(v.x));
            asm("cvt.rna.tf32.f32 %0, %1;" : "=r"(hi.y) : "f"(v.y));
            asm("cvt.rna.tf32.f32 %0, %1;" : "=r"(hi.z) : "f"(v.z));
            asm("cvt.rna.tf32.f32 %0, %1;" : "=r"(hi.w) : "f"(v.w));
            lo.x = __float_as_uint(v.x - __uint_as_float(hi.x));
            lo.y = __float_as_uint(v.y - __uint_as_float(hi.y));
            lo.z = __float_as_uint(v.z - __uint_as_float(hi.z));
            lo.w = __float_as_uint(v.w - __uint_as_float(hi.w));
            *(uint4*)(Ahi + r * ASTR + c4 * 4) = hi;
            *(uint4*)(Alo + r * ASTR + c4 * 4) = lo;
        }
        // ---- B fill: pre-split in global, straight uint4 copies ----
#pragma unroll
        for (int it = 0; it < 4; it++) {
            int idx = tid + it * 256;
            int r  = idx >> 5;                   // 32 uint4 per B row
            int c4 = idx & 31;
            size_t gsrc = (size_t)(kt + r) * NJ_ + j0 + c4 * 4;
            *(uint4*)(Bhi + r * BSTR + c4 * 4) = *(const uint4*)(g_Whi + gsrc);
            *(uint4*)(Blo + r * BSTR + c4 * 4) = *(const uint4*)(g_Wlo + gsrc);
        }
        __syncthreads();

#pragma unroll
        for (int ks = 0; ks < GBK; ks += 8) {
            uint32_t ahi[2][4], alo[2][4];
#pragma unroll
            for (int mt = 0; mt < 2; mt++) {
                int row = wm * 32 + mt * 16 + (lane >> 2);
                int col = ks + (lane & 3);
                ahi[mt][0] = Ahi[row * ASTR + col];
                alo[mt][0] = Alo[row * ASTR + col];
                ahi[mt][1] = Ahi[(row + 8) * ASTR + col];
                alo[mt][1] = Alo[(row + 8) * ASTR + col];
                ahi[mt][2] = Ahi[row * ASTR + col + 4];
                alo[mt][2] = Alo[row * ASTR + col + 4];
                ahi[mt][3] = Ahi[(row + 8) * ASTR + col + 4];
                alo[mt][3] = Alo[(row + 8) * ASTR + col + 4];
            }
            uint32_t bhi[8][2], blo[8][2];
#pragma unroll
            for (int nt = 0; nt < 8; nt++) {
                int cn = wn * 64 + nt * 8 + (lane >> 2);
                int rk = ks + (lane & 3);
                bhi[nt][0] = Bhi[rk * BSTR + cn];
                blo[nt][0] = Blo[rk * BSTR + cn];
                bhi[nt][1] = Bhi[(rk + 4) * BSTR + cn];
                blo[nt][1] = Blo[(rk + 4) * BSTR + cn];
            }
#pragma unroll
            for (int mt = 0; mt < 2; mt++)
#pragma unroll
                for (int nt = 0; nt < 8; nt++) {
                    mma_tf32(acc[mt][nt], ahi[mt], bhi[nt]);
                    mma_tf32(acc[mt][nt], alo[mt], bhi[nt]);
                    mma_tf32(acc[mt][nt], ahi[mt], blo[nt]);
                }
        }
    }

    // Epilogue: fragment (c0,c1)=(row, 2c..2c+1), (c2,c3)=(row+8, same cols)
#pragma unroll
    for (int mt = 0; mt < 2; mt++) {
        int row = r0 + wm * 32 + mt * 16 + (lane >> 2);
#pragma unroll
        for (int nt = 0; nt < 8; nt++) {
            int col = j0 + wn * 64 + nt * 8 + 2 * (lane & 3);
            float2 v0 = make_float2(acc[mt][nt][0], acc[mt][nt][1]);
            float2 v1 = make_float2(acc[mt][nt][2], acc[mt][nt][3]);
            *(float2*)(g_A + (size_t)row * NJ_ + col)       = v0;
            *(float2*)(g_A + (size_t)(row + 8) * NJ_ + col) = v1;
        }
    }
}

#define GEMM_SMEM ((GBM * ASTR * 2 + GBK * BSTR * 2) * 4)   // 71680 bytes

// ---------------------------------------------------------------------------
// K3: per-target TFN (unchanged from R12 — near its memory floor).
// ---------------------------------------------------------------------------
__global__ __launch_bounds__(256) void tfn_kernel(const float* __restrict__ points,
                                                  const float* __restrict__ b0)
{
    __shared__ float cY[4][32][16];
    __shared__ float cW[4][32][3];
    __shared__ int   cOff[4][32];
    __shared__ int   cCnt[4];
    __shared__ float hbuf[4][64][4];

    const int tid  = threadIdx.x;
    const int warp = tid >> 5;
    const int lane = tid & 31;
    const int tBase = blockIdx.x * 4;
    const int bb = tBase >> 9;     // batch (same for all 4 targets)

    if (warp < 4) {
        const int t = tBase + warp;
        const int m = t & 511;
        const float* pb = points + (size_t)bb * N_ * 3;
        const int nb = g_nbr[(size_t)t * KNN_ + lane];

        float w0s = 0.f, w1s = 0.f, w2s = 0.f;
        float Y[16];
#pragma unroll
        for (int i = 0; i < 16; i++) Y[i] = 0.f;

        if (nb >= 0) {
            const int src = m * 4;
            float rx = pb[nb * 3 + 0] - pb[src * 3 + 0];
            float ry = pb[nb * 3 + 1] - pb[src * 3 + 1];
            float rz = pb[nb * 3 + 2] - pb[src * 3 + 2];
            float d2 = rx * rx + ry * ry + rz * rz;
            float dist = sqrtf(fmaxf(d2, 1e-12f));
            float inv = 1.0f / dist;
            float x = rx * inv, y = ry * inv, z = rz * inv;
            float x2 = x * x, y2 = y * y, z2 = z * z;
            Y[0]  = 0.282095f;
            Y[1]  = 0.488603f * y;
            Y[2]  = 0.488603f * z;
            Y[3]  = 0.488603f * x;
            Y[4]  = 1.092548f * x * y;
            Y[5]  = 1.092548f * y * z;
            Y[6]  = 0.315392f * (3.0f * z2 - 1.0f);
            Y[7]  = 1.092548f * x * z;
            Y[8]  = 0.546274f * (x2 - y2);
            Y[9]  = 0.590044f * y * (3.0f * x2 - y2);
            Y[10] = 2.890611f * x * y * z;
            Y[11] = 0.457046f * y * (5.0f * z2 - 1.0f);
            Y[12] = 0.373176f * z * (5.0f * z2 - 3.0f);
            Y[13] = 0.457046f * x * (5.0f * z2 - 1.0f);
            Y[14] = 1.445306f * z * (x2 - y2);
            Y[15] = 0.590044f * x * (x2 - 3.0f * y2);

            float dn = dist * 2.5f;            // dist / RADIUS
            if (dn <= 1.0f) {
                const float G = 6.2383246250f; // ln2 * 9
                float d1 = dn - 0.5f;
                float dq = dn - 1.0f;
                w0s = expf(-G * dn * dn);
                w1s = expf(-G * d1 * d1);
                w2s = expf(-G * dq * dq);
            }
        }

        float s0 = w0s, s1 = w1s, s2 = w2s;
#pragma unroll
        for (int d = 16; d > 0; d >>= 1) {
            s0 += __shfl_xor_sync(0xffffffffu, s0, d);
            s1 += __shfl_xor_sync(0xffffffffu, s1, d);
            s2 += __shfl_xor_sync(0xffffffffu, s2, d);
        }

        bool act = (w0s + w1s + w2s) > 0.0f;   // dn<=1 && nb>=0
        unsigned msk = __ballot_sync(0xffffffffu, act);
        int pos = __popc(msk & ((1u << lane) - 1u));
        if (act) {
            cOff[warp][pos] = (bb * N_ + nb) * NJ_;
            cW[warp][pos][0] = w0s / (s0 + 1e-8f);
            cW[warp][pos][1] = w1s / (s1 + 1e-8f);
            cW[warp][pos][2] = w2s / (s2 + 1e-8f);
#pragma unroll
            for (int i = 0; i < 16; i++) cY[warp][pos][i] = Y[i];
        }
        if (lane == 0) cCnt[warp] = __popc(msk);
    }
    __syncthreads();

    const int tg = tid >> 6;          // target within block
    const int j  = tid & 63;
    const int l  = j >> 4;            // slab
    const int u0 = (j & 15) << 2;     // 4 units per thread
    const int baser = l * l;
    const int nr = 2 * l + 1;
    const int cnt = cCnt[tg];

    float ax[7], ay[7], az[7], aw[7];
#pragma unroll
    for (int r = 0; r < 7; r++) { ax[r] = 0.f; ay[r] = 0.f; az[r] = 0.f; aw[r] = 0.f; }

    const float* Abase = g_A + l * 192 + u0;
#pragma unroll 2
    for (int k = 0; k < cnt; k++) {
        const float* Ar = Abase + cOff[tg][k];
        float4 A0 = *(const float4*)(Ar);
        float4 A1 = *(const float4*)(Ar + 64);
        float4 A2 = *(const float4*)(Ar + 128);
        float w0 = cW[tg][k][0], w1 = cW[tg][k][1], w2 = cW[tg][k][2];
        float gx = w0 * A0.x + w1 * A1.x + w2 * A2.x;
        float gy = w0 * A0.y + w1 * A1.y + w2 * A2.y;
        float gz = w0 * A0.z + w1 * A1.z + w2 * A2.z;
        float gw = w0 * A0.w + w1 * A1.w + w2 * A2.w;
        const float* Yk = &cY[tg][k][baser];
#pragma unroll
        for (int r = 0; r < 7; r++)
            if (r < nr) {
                float y = Yk[r];
                ax[r] += y * gx; ay[r] += y * gy;
                az[r] += y * gz; aw[r] += y * gw;
            }
    }

    if (l == 0) {
        ax[0] += b0[u0 + 0]; ay[0] += b0[u0 + 1];
        az[0] += b0[u0 + 2]; aw[0] += b0[u0 + 3];
    }

    float sx = 0.f, sy = 0.f, sz = 0.f, sw = 0.f;
#pragma unroll
    for (int r = 0; r < 7; r++)
        if (r < nr) {
            sx += ax[r] * ax[r]; sy += ay[r] * ay[r];
            sz += az[r] * az[r]; sw += aw[r] * aw[r];
        }
    hbuf[tg][j][0] = sqrtf(fmaxf(sx, 1e-8f));
    hbuf[tg][j][1] = sqrtf(fmaxf(sy, 1e-8f));
    hbuf[tg][j][2] = sqrtf(fmaxf(sz, 1e-8f));
    hbuf[tg][j][3] = sqrtf(fmaxf(sw, 1e-8f));
    __syncthreads();

    {
        int jj = tid >> 2;            // 0..63
        int cc = tid & 3;             // 0..3
        float h = fmaxf(fmaxf(hbuf[0][jj][cc], hbuf[1][jj][cc]),
                        fmaxf(hbuf[2][jj][cc], hbuf[3][jj][cc]));
        int ll = jj >> 4;
        int uu = ((jj & 15) << 2) + cc;
        // h > 0 always, so int-compare == float-compare
        atomicMax((int*)&g_H[bb * 256 + ll * 64 + uu], __float_as_int(h));
    }
}

// ---------------------------------------------------------------------------
// K4: MLP head + softmax, float4 weight loads, full-block k-split partials.
// ---------------------------------------------------------------------------
__global__ __launch_bounds__(256) void mlp_kernel(
    const float* __restrict__ Wfc1, const float* __restrict__ bfc1,
    const float* __restrict__ Wfc2, const float* __restrict__ bfc2,
    const float* __restrict__ Wsm,  const float* __restrict__ bsm,
    float* __restrict__ out)
{
    __shared__ float  sH[256];
    __shared__ float4 part[256];
    __shared__ float  s1[512];
    __shared__ float  s2[256];
    __shared__ float  sl[40];

    const int b = blockIdx.x;
    const int t = threadIdx.x;

    sH[t] = g_H[b * 256 + t];
    __syncthreads();

    // ---- fc1: 512 outputs; u4 = t&127, k-half = t>>7 ----
    {
        const int u4 = t & 127;
        const int k0 = (t >> 7) * 128;
        const float4* W4 = (const float4*)Wfc1;   // [k][128]
        float4 a = make_float4(0.f, 0.f, 0.f, 0.f);
#pragma unroll 4
        for (int k = k0; k < k0 + 128; k++) {
            float h = sH[k];
            float4 w = W4[k * 128 + u4];
            a.x += h * w.x; a.y += h * w.y; a.z += h * w.z; a.w += h * w.w;
        }
        part[t] = a;
    }
    __syncthreads();
    if (t < 128) {
        float4 a = part[t], c = part[t + 128];
        float4 bias = ((const float4*)bfc1)[t];
        float4 r;
        r.x = fmaxf(a.x + c.x + bias.x, 0.f);
        r.y = fmaxf(a.y + c.y + bias.y, 0.f);
        r.z = fmaxf(a.z + c.z + bias.z, 0.f);
        r.w = fmaxf(a.w + c.w + bias.w, 0.f);
        ((float4*)s1)[t] = r;
    }
    __syncthreads();

    // ---- fc2: 256 outputs; u4 = t&63, 4-way k-split ----
    {
        const int u4 = t & 63;
        const int k0 = (t >> 6) * 128;
        const float4* W4 = (const float4*)Wfc2;   // [k][64]
        float4 a = make_float4(0.f, 0.f, 0.f, 0.f);
#pragma unroll 4
        for (int k = k0; k < k0 + 128; k++) {
            float h = s1[k];
            float4 w = W4[k * 64 + u4];
            a.x += h * w.x; a.y += h * w.y; a.z += h * w.z; a.w += h * w.w;
        }
        part[t] = a;
    }
    __syncthreads();
    if (t < 64) {
        float4 a0 = part[t], a1 = part[t + 64], a2 = part[t + 128], a3 = part[t + 192];
        float4 bias = ((const float4*)bfc2)[t];
        float4 r;
        r.x = fmaxf(a0.x + a1.x + a2.x + a3.x + bias.x, 0.f);
        r.y = fmaxf(a0.y + a1.y + a2.y + a3.y + bias.y, 0.f);
        r.z = fmaxf(a0.z + a1.z + a2.z + a3.z + bias.z, 0.f);
        r.w = fmaxf(a0.w + a1.w + a2.w + a3.w + bias.w, 0.f);
        ((float4*)s2)[t] = r;
    }
    __syncthreads();

    // ---- fc3: 40 outputs; u4 = t>>3 (0..9), 8-way k-split (t<80) ----
    if (t < 80) {
        const int u4 = t >> 3;
        const int k0 = (t & 7) * 32;
        const float4* W4 = (const float4*)Wsm;    // [k][10]
        float4 a = make_float4(0.f, 0.f, 0.f, 0.f);
#pragma unroll 4
        for (int k = k0; k < k0 + 32; k++) {
            float h = s2[k];
            float4 w = W4[k * 10 + u4];
            a.x += h * w.x; a.y += h * w.y; a.z += h * w.z; a.w += h * w.w;
        }
        part[t] = a;
    }
    __syncthreads();
    if (t < 10) {
        float4 a = make_float4(0.f, 0.f, 0.f, 0.f);
#pragma unroll
        for (int ks = 0; ks < 8; ks++) {
            float4 p = part[t * 8 + ks];
            a.x += p.x; a.y += p.y; a.z += p.z; a.w += p.w;
        }
        float4 bias = ((const float4*)bsm)[t];
        sl[t * 4 + 0] = a.x + bias.x;
        sl[t * 4 + 1] = a.y + bias.y;
        sl[t * 4 + 2] = a.z + bias.z;
        sl[t * 4 + 3] = a.w + bias.w;
    }
    __syncthreads();

    if (t == 0) {
        float mx = -1e30f;
        for (int i = 0; i < 40; i++) mx = fmaxf(mx, sl[i]);
        float s = 0.0f;
        for (int i = 0; i < 40; i++) { float e = expf(sl[i] - mx); sl[i] = e; s += e; }
        float invs = 1.0f / s;
        for (int i = 0; i < 40; i++) out[b * 40 + i] = sl[i] * invs;
    }
}

// ---------------------------------------------------------------------------
// launch
// ---------------------------------------------------------------------------
extern "C" void kernel_launch(void* const* d_in, const int* in_sizes, int n_in,
                              void* d_out, int out_size)
{
    const float* points = (const float*)d_in[0];
    const float* feats  = (const float*)d_in[1];
    const float* W0     = (const float*)d_in[2];
    const float* b0     = (const float*)d_in[3];
    const float* W1     = (const float*)d_in[4];
    const float* W2     = (const float*)d_in[5];
    const float* W3     = (const float*)d_in[6];
    const float* Wfc1   = (const float*)d_in[7];
    const float* bfc1   = (const float*)d_in[8];
    const float* Wfc2   = (const float*)d_in[9];
    const float* bfc2   = (const float*)d_in[10];
    const float* Wsm    = (const float*)d_in[11];
    const float* bsm    = (const float*)d_in[12];
    float* out = (float*)d_out;

    static bool attr_done = false;
    if (!attr_done) {
        cudaFuncSetAttribute(gemm_tc_kernel,
                             cudaFuncAttributeMaxDynamicSharedMemorySize, GEMM_SMEM);
        attr_done = true;
    }

    prep_kernel<<<192, 256>>>(W0, W1, W2, W3);
    knn_kernel<<<dim3(M_ / 8, B_), 256>>>(points);
    gemm_tc_kernel<<<dim3(NPTS_ / GBM, NJ_ / GBN), 256, GEMM_SMEM>>>(feats);
    tfn_kernel<<<T_ / 4, 256>>>(points, b0);
    mlp_kernel<<<B_, 256>>>(Wfc1, bfc1, Wfc2, bfc2, Wsm, bsm, out);
}

// round 15
// speedup vs baseline: 1.6606x; 1.0789x over previous
#include <cuda_runtime.h>
#include <cuda_bf16.h>
#include <math.h>
#include <stdint.h>

// ---------------------------------------------------------------------------
// Problem constants
// ---------------------------------------------------------------------------
#define B_      32
#define N_      2048
#define M_      512            // N_/STRIDE
#define T_      (B_ * M_)      // 16384 targets
#define C_      64
#define KNN_    32
#define NJ_     768            // 4 slabs * 3 shells * 64 units
#define NPTS_   (B_ * N_)      // 65536

// Scratch (allowed: __device__ globals, no runtime allocation)
__device__ float    g_A[(size_t)NPTS_ * NJ_];   // point-level transformed features
__device__ uint32_t g_Wh[NJ_ * C_ / 2];         // weights [n][k-pair], bf16x2 hi
__device__ uint32_t g_Wm[NJ_ * C_ / 2];         // weights [n][k-pair], bf16x2 mid
__device__ int      g_nbr[T_ * KNN_];           // neighbor indices, -1 padded
__device__ float    g_H[B_ * 256];              // max-pooled features

__device__ __forceinline__ uint32_t pack_bf16x2(__nv_bfloat16 lo, __nv_bfloat16 hi)
{
    __nv_bfloat162 t;
    t.x = lo; t.y = hi;           // .x occupies low 16 bits (first/even k)
    return *(uint32_t*)&t;
}

// ---------------------------------------------------------------------------
// K0: repack W0..W3 into B layout [n][k] (n=(l,s,u), k=c), pre-split into
// bf16 hi + bf16 mid (residual), packed as bf16x2 per k-pair. Zero g_H.
// ---------------------------------------------------------------------------
__global__ void prep_kernel(const float* __restrict__ W0, const float* __restrict__ W1,
                            const float* __restrict__ W2, const float* __restrict__ W3)
{
    int tid = blockIdx.x * blockDim.x + threadIdx.x;
    if (tid < B_ * 256) g_H[tid] = 0.0f;
    if (tid < NJ_ * (C_ / 2)) {
        int n  = tid >> 5;            // 0..767
        int pr = tid & 31;            // k-pair 0..31
        int l = n / 192;
        int r = n - l * 192;
        int s = r >> 6;
        int u = r & 63;
        const float* W = (l == 0) ? W0 : (l == 1) ? W1 : (l == 2) ? W2 : W3;
        float w0 = W[(s * 64 + 2 * pr + 0) * 64 + u];
        float w1 = W[(s * 64 + 2 * pr + 1) * 64 + u];
        __nv_bfloat16 h0 = __float2bfloat16(w0);
        __nv_bfloat16 h1 = __float2bfloat16(w1);
        __nv_bfloat16 m0 = __float2bfloat16(w0 - __bfloat162float(h0));
        __nv_bfloat16 m1 = __float2bfloat16(w1 - __bfloat162float(h1));
        g_Wh[tid] = pack_bf16x2(h0, h1);
        g_Wm[tid] = pack_bf16x2(m0, m1);
    }
}

// ---------------------------------------------------------------------------
// K1: KNN via radius filter + exact rank-select fallback (unchanged; correct).
// ---------------------------------------------------------------------------
__global__ __launch_bounds__(256) void knn_kernel(const float* __restrict__ points)
{
    __shared__ float sp[N_ * 3];
    __shared__ float sd2[8][256];
    __shared__ int   sidx[8][256];

    const int b = blockIdx.y;
    const float* pb = points + (size_t)b * N_ * 3;
    for (int i = threadIdx.x; i < N_ * 3; i += 256) sp[i] = pb[i];
    __syncthreads();

    const int warp = threadIdx.x >> 5;
    const int lane = threadIdx.x & 31;
    const int m = blockIdx.x * 8 + warp;
    const int src = m * 4;

    const float tx = sp[src * 3 + 0];
    const float ty = sp[src * 3 + 1];
    const float tz = sp[src * 3 + 2];

    const float TH = 0.16f * 1.00002f;

    int base = 0;
    for (int c = lane; c < N_; c += 32) {
        float dx = sp[c * 3 + 0] - tx;
        float dy = sp[c * 3 + 1] - ty;
        float dz = sp[c * 3 + 2] - tz;
        float d2 = dx * dx + dy * dy + dz * dz;
        bool p = (d2 <= TH);
        unsigned msk = __ballot_sync(0xffffffffu, p);
        if (p) {
            int pos = base + __popc(msk & ((1u << lane) - 1u));
            if (pos < 256) { sd2[warp][pos] = d2; sidx[warp][pos] = c; }
        }
        base += __popc(msk);
    }
    int cnt = min(base, 256);
    __syncwarp();

    int* out = g_nbr + (size_t)(b * M_ + m) * KNN_;
    if (cnt <= KNN_) {
        out[lane] = (lane < cnt) ? sidx[warp][lane] : -1;
    } else {
        for (int i = lane; i < cnt; i += 32) {
            float di = sd2[warp][i];
            int rank = 0;
            for (int jj = 0; jj < cnt; jj++) {
                float dj = sd2[warp][jj];
                rank += (dj < di) || (dj == di && jj < i);
            }
            if (rank < KNN_) out[rank] = sidx[warp][i];
        }
    }
}

// ---------------------------------------------------------------------------
// K2: A = feats @ W via mma.sync.m16n8k16 bf16, 3xBF16 (hi*hi + hi*mid + mid*hi).
// Block tile 128x64, warp tile 32x32 (8 warps = 4M x 2N), single K=64 pass.
// Smem as uint32 bf16x2 pairs, stride 36 words -> conflict-free frag LDS.
// ---------------------------------------------------------------------------
#define GBM 128
#define GBN 64
#define KW  32          // K in bf16x2 words (64 halves)
#define STR 36          // 32 + 4 pad: banks (4*row + pair) all distinct

__device__ __forceinline__ void mma_bf16(float* d, const uint32_t* a, const uint32_t* b)
{
    asm volatile(
        "mma.sync.aligned.m16n8k16.row.col.f32.bf16.bf16.f32 "
        "{%0,%1,%2,%3},{%4,%5,%6,%7},{%8,%9},{%0,%1,%2,%3};\n"
        : "+f"(d[0]), "+f"(d[1]), "+f"(d[2]), "+f"(d[3])
        : "r"(a[0]), "r"(a[1]), "r"(a[2]), "r"(a[3]), "r"(b[0]), "r"(b[1]));
}

__global__ __launch_bounds__(256, 3) void gemm_tc_kernel(const float* __restrict__ feats)
{
    extern __shared__ uint32_t smem_g[];
    uint32_t* Ah = smem_g;                 // [GBM][STR]
    uint32_t* Am = Ah + GBM * STR;         // [GBM][STR]
    uint32_t* Bh = Am + GBM * STR;         // [GBN][STR]
    uint32_t* Bm = Bh + GBN * STR;         // [GBN][STR]

    const int tid  = threadIdx.x;
    const int warp = tid >> 5;
    const int lane = tid & 31;
    const int wm   = warp & 3;     // 0..3 (M)
    const int wn   = warp >> 2;    // 0..1 (N)
    const int r0   = blockIdx.x * GBM;
    const int j0   = blockIdx.y * GBN;

    // ---- A fill: 128 rows x 64 k = 2048 float4; split to bf16 hi/mid pairs ----
#pragma unroll
    for (int it = 0; it < 8; it++) {
        int idx = tid + it * 256;          // 0..2047
        int r  = idx >> 4;                 // 16 float4 per row
        int c4 = idx & 15;
        float4 v = *(const float4*)(feats + (size_t)(r0 + r) * C_ + c4 * 4);
        __nv_bfloat16 hx = __float2bfloat16(v.x), hy = __float2bfloat16(v.y);
        __nv_bfloat16 hz = __float2bfloat16(v.z), hw = __float2bfloat16(v.w);
        __nv_bfloat16 mx = __float2bfloat16(v.x - __bfloat162float(hx));
        __nv_bfloat16 my = __float2bfloat16(v.y - __bfloat162float(hy));
        __nv_bfloat16 mz = __float2bfloat16(v.z - __bfloat162float(hz));
        __nv_bfloat16 mw = __float2bfloat16(v.w - __bfloat162float(hw));
        uint2 hvec = make_uint2(pack_bf16x2(hx, hy), pack_bf16x2(hz, hw));
        uint2 mvec = make_uint2(pack_bf16x2(mx, my), pack_bf16x2(mz, mw));
        *(uint2*)(Ah + r * STR + c4 * 2) = hvec;
        *(uint2*)(Am + r * STR + c4 * 2) = mvec;
    }
    // ---- B fill: 64 n-rows x 32 pairs = 512 uint4-chunks/4 ----
#pragma unroll
    for (int it = 0; it < 2; it++) {
        int idx = tid + it * 256;          // 0..511
        int n  = idx >> 3;
        int p4 = idx & 7;
        size_t gsrc = (size_t)(j0 + n) * KW + p4 * 4;
        *(uint4*)(Bh + n * STR + p4 * 4) = *(const uint4*)(g_Wh + gsrc);
        *(uint4*)(Bm + n * STR + p4 * 4) = *(const uint4*)(g_Wm + gsrc);
    }
    __syncthreads();

    float acc[2][4][4];
#pragma unroll
    for (int mt = 0; mt < 2; mt++)
#pragma unroll
        for (int nt = 0; nt < 4; nt++)
#pragma unroll
            for (int i = 0; i < 4; i++) acc[mt][nt][i] = 0.0f;

#pragma unroll
    for (int ks = 0; ks < 4; ks++) {                 // 4 x k16 steps
        const int bp = ks * 8 + (lane & 3);          // base k-pair
        uint32_t ah[2][4], am[2][4];
#pragma unroll
        for (int mt = 0; mt < 2; mt++) {
            int row = wm * 32 + mt * 16 + (lane >> 2);
            ah[mt][0] = Ah[row * STR + bp];
            ah[mt][1] = Ah[(row + 8) * STR + bp];
            ah[mt][2] = Ah[row * STR + bp + 4];
            ah[mt][3] = Ah[(row + 8) * STR + bp + 4];
            am[mt][0] = Am[row * STR + bp];
            am[mt][1] = Am[(row + 8) * STR + bp];
            am[mt][2] = Am[row * STR + bp + 4];
            am[mt][3] = Am[(row + 8) * STR + bp + 4];
        }
        uint32_t bh[4][2], bm[4][2];
#pragma unroll
        for (int nt = 0; nt < 4; nt++) {
            int cn = wn * 32 + nt * 8 + (lane >> 2);
            bh[nt][0] = Bh[cn * STR + bp];
            bh[nt][1] = Bh[cn * STR + bp + 4];
            bm[nt][0] = Bm[cn * STR + bp];
            bm[nt][1] = Bm[cn * STR + bp + 4];
        }
#pragma unroll
        for (int mt = 0; mt < 2; mt++)
#pragma unroll
            for (int nt = 0; nt < 4; nt++) {
                mma_bf16(acc[mt][nt], ah[mt], bh[nt]);
                mma_bf16(acc[mt][nt], am[mt], bh[nt]);
                mma_bf16(acc[mt][nt], ah[mt], bm[nt]);
            }
    }

    // Epilogue: (c0,c1)=(row, 2c..2c+1), (c2,c3)=(row+8, same cols)
#pragma unroll
    for (int mt = 0; mt < 2; mt++) {
        int row = r0 + wm * 32 + mt * 16 + (lane >> 2);
#pragma unroll
        for (int nt = 0; nt < 4; nt++) {
            int col = j0 + wn * 32 + nt * 8 + 2 * (lane & 3);
            float2 v0 = make_float2(acc[mt][nt][0], acc[mt][nt][1]);
            float2 v1 = make_float2(acc[mt][nt][2], acc[mt][nt][3]);
            *(float2*)(g_A + (size_t)row * NJ_ + col)       = v0;
            *(float2*)(g_A + (size_t)(row + 8) * NJ_ + col) = v1;
        }
    }
}

#define GEMM_SMEM ((GBM * STR * 2 + GBN * STR * 2) * 4)   // 55296 bytes

// ---------------------------------------------------------------------------
// K3: per-target TFN (R12 structure; launch_bounds(256,5) for 62.5% occ).
// ---------------------------------------------------------------------------
__global__ __launch_bounds__(256, 5) void tfn_kernel(const float* __restrict__ points,
                                                     const float* __restrict__ b0)
{
    __shared__ float cY[4][32][16];
    __shared__ float cW[4][32][3];
    __shared__ int   cOff[4][32];
    __shared__ int   cCnt[4];
    __shared__ float hbuf[4][64][4];

    const int tid  = threadIdx.x;
    const int warp = tid >> 5;
    const int lane = tid & 31;
    const int tBase = blockIdx.x * 4;
    const int bb = tBase >> 9;     // batch (same for all 4 targets)

    if (warp < 4) {
        const int t = tBase + warp;
        const int m = t & 511;
        const float* pb = points + (size_t)bb * N_ * 3;
        const int nb = g_nbr[(size_t)t * KNN_ + lane];

        float w0s = 0.f, w1s = 0.f, w2s = 0.f;
        float Y[16];
#pragma unroll
        for (int i = 0; i < 16; i++) Y[i] = 0.f;

        if (nb >= 0) {
            const int src = m * 4;
            float rx = pb[nb * 3 + 0] - pb[src * 3 + 0];
            float ry = pb[nb * 3 + 1] - pb[src * 3 + 1];
            float rz = pb[nb * 3 + 2] - pb[src * 3 + 2];
            float d2 = rx * rx + ry * ry + rz * rz;
            float dist = sqrtf(fmaxf(d2, 1e-12f));
            float inv = 1.0f / dist;
            float x = rx * inv, y = ry * inv, z = rz * inv;
            float x2 = x * x, y2 = y * y, z2 = z * z;
            Y[0]  = 0.282095f;
            Y[1]  = 0.488603f * y;
            Y[2]  = 0.488603f * z;
            Y[3]  = 0.488603f * x;
            Y[4]  = 1.092548f * x * y;
            Y[5]  = 1.092548f * y * z;
            Y[6]  = 0.315392f * (3.0f * z2 - 1.0f);
            Y[7]  = 1.092548f * x * z;
            Y[8]  = 0.546274f * (x2 - y2);
            Y[9]  = 0.590044f * y * (3.0f * x2 - y2);
            Y[10] = 2.890611f * x * y * z;
            Y[11] = 0.457046f * y * (5.0f * z2 - 1.0f);
            Y[12] = 0.373176f * z * (5.0f * z2 - 3.0f);
            Y[13] = 0.457046f * x * (5.0f * z2 - 1.0f);
            Y[14] = 1.445306f * z * (x2 - y2);
            Y[15] = 0.590044f * x * (x2 - 3.0f * y2);

            float dn = dist * 2.5f;            // dist / RADIUS
            if (dn <= 1.0f) {
                const float G = 6.2383246250f; // ln2 * 9
                float d1 = dn - 0.5f;
                float dq = dn - 1.0f;
                w0s = expf(-G * dn * dn);
                w1s = expf(-G * d1 * d1);
                w2s = expf(-G * dq * dq);
            }
        }

        float s0 = w0s, s1 = w1s, s2 = w2s;
#pragma unroll
        for (int d = 16; d > 0; d >>= 1) {
            s0 += __shfl_xor_sync(0xffffffffu, s0, d);
            s1 += __shfl_xor_sync(0xffffffffu, s1, d);
            s2 += __shfl_xor_sync(0xffffffffu, s2, d);
        }

        bool act = (w0s + w1s + w2s) > 0.0f;   // dn<=1 && nb>=0
        unsigned msk = __ballot_sync(0xffffffffu, act);
        int pos = __popc(msk & ((1u << lane) - 1u));
        if (act) {
            cOff[warp][pos] = (bb * N_ + nb) * NJ_;
            cW[warp][pos][0] = w0s / (s0 + 1e-8f);
            cW[warp][pos][1] = w1s / (s1 + 1e-8f);
            cW[warp][pos][2] = w2s / (s2 + 1e-8f);
#pragma unroll
            for (int i = 0; i < 16; i++) cY[warp][pos][i] = Y[i];
        }
        if (lane == 0) cCnt[warp] = __popc(msk);
    }
    __syncthreads();

    const int tg = tid >> 6;          // target within block
    const int j  = tid & 63;
    const int l  = j >> 4;            // slab
    const int u0 = (j & 15) << 2;     // 4 units per thread
    const int baser = l * l;
    const int nr = 2 * l + 1;
    const int cnt = cCnt[tg];

    float ax[7], ay[7], az[7], aw[7];
#pragma unroll
    for (int r = 0; r < 7; r++) { ax[r] = 0.f; ay[r] = 0.f; az[r] = 0.f; aw[r] = 0.f; }

    const float* Abase = g_A + l * 192 + u0;
#pragma unroll 2
    for (int k = 0; k < cnt; k++) {
        const float* Ar = Abase + cOff[tg][k];
        float4 A0 = *(const float4*)(Ar);
        float4 A1 = *(const float4*)(Ar + 64);
        float4 A2 = *(const float4*)(Ar + 128);
        float w0 = cW[tg][k][0], w1 = cW[tg][k][1], w2 = cW[tg][k][2];
        float gx = w0 * A0.x + w1 * A1.x + w2 * A2.x;
        float gy = w0 * A0.y + w1 * A1.y + w2 * A2.y;
        float gz = w0 * A0.z + w1 * A1.z + w2 * A2.z;
        float gw = w0 * A0.w + w1 * A1.w + w2 * A2.w;
        const float* Yk = &cY[tg][k][baser];
#pragma unroll
        for (int r = 0; r < 7; r++)
            if (r < nr) {
                float y = Yk[r];
                ax[r] += y * gx; ay[r] += y * gy;
                az[r] += y * gz; aw[r] += y * gw;
            }
    }

    if (l == 0) {
        ax[0] += b0[u0 + 0]; ay[0] += b0[u0 + 1];
        az[0] += b0[u0 + 2]; aw[0] += b0[u0 + 3];
    }

    float sx = 0.f, sy = 0.f, sz = 0.f, sw = 0.f;
#pragma unroll
    for (int r = 0; r < 7; r++)
        if (r < nr) {
            sx += ax[r] * ax[r]; sy += ay[r] * ay[r];
            sz += az[r] * az[r]; sw += aw[r] * aw[r];
        }
    hbuf[tg][j][0] = sqrtf(fmaxf(sx, 1e-8f));
    hbuf[tg][j][1] = sqrtf(fmaxf(sy, 1e-8f));
    hbuf[tg][j][2] = sqrtf(fmaxf(sz, 1e-8f));
    hbuf[tg][j][3] = sqrtf(fmaxf(sw, 1e-8f));
    __syncthreads();

    {
        int jj = tid >> 2;            // 0..63
        int cc = tid & 3;             // 0..3
        float h = fmaxf(fmaxf(hbuf[0][jj][cc], hbuf[1][jj][cc]),
                        fmaxf(hbuf[2][jj][cc], hbuf[3][jj][cc]));
        int ll = jj >> 4;
        int uu = ((jj & 15) << 2) + cc;
        // h > 0 always, so int-compare == float-compare
        atomicMax((int*)&g_H[bb * 256 + ll * 64 + uu], __float_as_int(h));
    }
}

// ---------------------------------------------------------------------------
// K4: MLP head + softmax, float4 weight loads, full-block k-split partials.
// ---------------------------------------------------------------------------
__global__ __launch_bounds__(256) void mlp_kernel(
    const float* __restrict__ Wfc1, const float* __restrict__ bfc1,
    const float* __restrict__ Wfc2, const float* __restrict__ bfc2,
    const float* __restrict__ Wsm,  const float* __restrict__ bsm,
    float* __restrict__ out)
{
    __shared__ float  sH[256];
    __shared__ float4 part[256];
    __shared__ float  s1[512];
    __shared__ float  s2[256];
    __shared__ float  sl[40];

    const int b = blockIdx.x;
    const int t = threadIdx.x;

    sH[t] = g_H[b * 256 + t];
    __syncthreads();

    {
        const int u4 = t & 127;
        const int k0 = (t >> 7) * 128;
        const float4* W4 = (const float4*)Wfc1;   // [k][128]
        float4 a = make_float4(0.f, 0.f, 0.f, 0.f);
#pragma unroll 4
        for (int k = k0; k < k0 + 128; k++) {
            float h = sH[k];
            float4 w = W4[k * 128 + u4];
            a.x += h * w.x; a.y += h * w.y; a.z += h * w.z; a.w += h * w.w;
        }
        part[t] = a;
    }
    __syncthreads();
    if (t < 128) {
        float4 a = part[t], c = part[t + 128];
        float4 bias = ((const float4*)bfc1)[t];
        float4 r;
        r.x = fmaxf(a.x + c.x + bias.x, 0.f);
        r.y = fmaxf(a.y + c.y + bias.y, 0.f);
        r.z = fmaxf(a.z + c.z + bias.z, 0.f);
        r.w = fmaxf(a.w + c.w + bias.w, 0.f);
        ((float4*)s1)[t] = r;
    }
    __syncthreads();

    {
        const int u4 = t & 63;
        const int k0 = (t >> 6) * 128;
        const float4* W4 = (const float4*)Wfc2;   // [k][64]
        float4 a = make_float4(0.f, 0.f, 0.f, 0.f);
#pragma unroll 4
        for (int k = k0; k < k0 + 128; k++) {
            float h = s1[k];
            float4 w = W4[k * 64 + u4];
            a.x += h * w.x; a.y += h * w.y; a.z += h * w.z; a.w += h * w.w;
        }
        part[t] = a;
    }
    __syncthreads();
    if (t < 64) {
        float4 a0 = part[t], a1 = part[t + 64], a2 = part[t + 128], a3 = part[t + 192];
        float4 bias = ((const float4*)bfc2)[t];
        float4 r;
        r.x = fmaxf(a0.x + a1.x + a2.x + a3.x + bias.x, 0.f);
        r.y = fmaxf(a0.y + a1.y + a2.y + a3.y + bias.y, 0.f);
        r.z = fmaxf(a0.z + a1.z + a2.z + a3.z + bias.z, 0.f);
        r.w = fmaxf(a0.w + a1.w + a2.w + a3.w + bias.w, 0.f);
        ((float4*)s2)[t] = r;
    }
    __syncthreads();

    if (t < 80) {
        const int u4 = t >> 3;
        const int k0 = (t & 7) * 32;
        const float4* W4 = (const float4*)Wsm;    // [k][10]
        float4 a = make_float4(0.f, 0.f, 0.f, 0.f);
#pragma unroll 4
        for (int k = k0; k < k0 + 32; k++) {
            float h = s2[k];
            float4 w = W4[k * 10 + u4];
            a.x += h * w.x; a.y += h * w.y; a.z += h * w.z; a.w += h * w.w;
        }
        part[t] = a;
    }
    __syncthreads();
    if (t < 10) {
        float4 a = make_float4(0.f, 0.f, 0.f, 0.f);
#pragma unroll
        for (int ks = 0; ks < 8; ks++) {
            float4 p = part[t * 8 + ks];
            a.x += p.x; a.y += p.y; a.z += p.z; a.w += p.w;
        }
        float4 bias = ((const float4*)bsm)[t];
        sl[t * 4 + 0] = a.x + bias.x;
        sl[t * 4 + 1] = a.y + bias.y;
        sl[t * 4 + 2] = a.z + bias.z;
        sl[t * 4 + 3] = a.w + bias.w;
    }
    __syncthreads();

    if (t == 0) {
        float mx = -1e30f;
        for (int i = 0; i < 40; i++) mx = fmaxf(mx, sl[i]);
        float s = 0.0f;
        for (int i = 0; i < 40; i++) { float e = expf(sl[i] - mx); sl[i] = e; s += e; }
        float invs = 1.0f / s;
        for (int i = 0; i < 40; i++) out[b * 40 + i] = sl[i] * invs;
    }
}

// ---------------------------------------------------------------------------
// launch
// ---------------------------------------------------------------------------
extern "C" void kernel_launch(void* const* d_in, const int* in_sizes, int n_in,
                              void* d_out, int out_size)
{
    const float* points = (const float*)d_in[0];
    const float* feats  = (const float*)d_in[1];
    const float* W0     = (const float*)d_in[2];
    const float* b0     = (const float*)d_in[3];
    const float* W1     = (const float*)d_in[4];
    const float* W2     = (const float*)d_in[5];
    const float* W3     = (const float*)d_in[6];
    const float* Wfc1   = (const float*)d_in[7];
    const float* bfc1   = (const float*)d_in[8];
    const float* Wfc2   = (const float*)d_in[9];
    const float* bfc2   = (const float*)d_in[10];
    const float* Wsm    = (const float*)d_in[11];
    const float* bsm    = (const float*)d_in[12];
    float* out = (float*)d_out;

    static bool attr_done = false;
    if (!attr_done) {
        cudaFuncSetAttribute(gemm_tc_kernel,
                             cudaFuncAttributeMaxDynamicSharedMemorySize, GEMM_SMEM);
        attr_done = true;
    }

    prep_kernel<<<96, 256>>>(W0, W1, W2, W3);
    knn_kernel<<<dim3(M_ / 8, B_), 256>>>(points);
    gemm_tc_kernel<<<dim3(NPTS_ / GBM, NJ_ / GBN), 256, GEMM_SMEM>>>(feats);
    tfn_kernel<<<T_ / 4, 256>>>(points, b0);
    mlp_kernel<<<B_, 256>>>(Wfc1, bfc1, Wfc2, bfc2, Wsm, bsm, out);
}

// round 16
// speedup vs baseline: 1.8267x; 1.1000x over previous
#include <cuda_runtime.h>
#include <cuda_bf16.h>
#include <math.h>
#include <stdint.h>

// ---------------------------------------------------------------------------
// Problem constants
// ---------------------------------------------------------------------------
#define B_      32
#define N_      2048
#define M_      512            // N_/STRIDE
#define T_      (B_ * M_)      // 16384 targets
#define C_      64
#define KNN_    32
#define NJ_     768            // 4 slabs * 3 shells * 64 units
#define NPTS_   (B_ * N_)      // 65536

// Scratch (allowed: __device__ globals, no runtime allocation)
__device__ float    g_A[(size_t)NPTS_ * NJ_];   // point-level transformed features
__device__ uint32_t g_Wh[NJ_ * C_ / 2];         // weights [n][k-pair], bf16x2 hi
__device__ uint32_t g_Wm[NJ_ * C_ / 2];         // weights [n][k-pair], bf16x2 mid
__device__ uint32_t g_Fh[(size_t)NPTS_ * (C_ / 2)];  // feats bf16x2 hi  [row][pair]
__device__ uint32_t g_Fm[(size_t)NPTS_ * (C_ / 2)];  // feats bf16x2 mid [row][pair]
__device__ int      g_nbr[T_ * KNN_];           // neighbor indices, -1 padded
__device__ float    g_H[B_ * 256];              // max-pooled features

__device__ __forceinline__ uint32_t pack_bf16x2(__nv_bfloat16 lo, __nv_bfloat16 hi)
{
    __nv_bfloat162 t;
    t.x = lo; t.y = hi;           // .x occupies low 16 bits (first/even k)
    return *(uint32_t*)&t;
}

// ---------------------------------------------------------------------------
// K0: repack W0..W3 into B layout [n][k] (n=(l,s,u), k=c), pre-split into
// bf16 hi + bf16 mid (residual), packed as bf16x2 per k-pair. Zero g_H.
// ---------------------------------------------------------------------------
__global__ void prep_kernel(const float* __restrict__ W0, const float* __restrict__ W1,
                            const float* __restrict__ W2, const float* __restrict__ W3)
{
    int tid = blockIdx.x * blockDim.x + threadIdx.x;
    if (tid < B_ * 256) g_H[tid] = 0.0f;
    if (tid < NJ_ * (C_ / 2)) {
        int n  = tid >> 5;            // 0..767
        int pr = tid & 31;            // k-pair 0..31
        int l = n / 192;
        int r = n - l * 192;
        int s = r >> 6;
        int u = r & 63;
        const float* W = (l == 0) ? W0 : (l == 1) ? W1 : (l == 2) ? W2 : W3;
        float w0 = W[(s * 64 + 2 * pr + 0) * 64 + u];
        float w1 = W[(s * 64 + 2 * pr + 1) * 64 + u];
        __nv_bfloat16 h0 = __float2bfloat16(w0);
        __nv_bfloat16 h1 = __float2bfloat16(w1);
        __nv_bfloat16 m0 = __float2bfloat16(w0 - __bfloat162float(h0));
        __nv_bfloat16 m1 = __float2bfloat16(w1 - __bfloat162float(h1));
        g_Wh[tid] = pack_bf16x2(h0, h1);
        g_Wm[tid] = pack_bf16x2(m0, m1);
    }
}

// ---------------------------------------------------------------------------
// K0b: one-shot feats split: fp32 -> bf16 hi + bf16 mid, packed per k-pair.
// One float4 per thread. Replaces the 12x-redundant per-block split in gemm.
// ---------------------------------------------------------------------------
__global__ __launch_bounds__(256) void split_feats_kernel(const float* __restrict__ feats)
{
    int idx = blockIdx.x * blockDim.x + threadIdx.x;   // 0 .. NPTS_*16-1
    int row = idx >> 4;              // 16 float4 per row
    int c4  = idx & 15;
    float4 v = *(const float4*)(feats + (size_t)row * C_ + c4 * 4);
    __nv_bfloat16 hx = __float2bfloat16(v.x), hy = __float2bfloat16(v.y);
    __nv_bfloat16 hz = __float2bfloat16(v.z), hw = __float2bfloat16(v.w);
    __nv_bfloat16 mx = __float2bfloat16(v.x - __bfloat162float(hx));
    __nv_bfloat16 my = __float2bfloat16(v.y - __bfloat162float(hy));
    __nv_bfloat16 mz = __float2bfloat16(v.z - __bfloat162float(hz));
    __nv_bfloat16 mw = __float2bfloat16(v.w - __bfloat162float(hw));
    size_t w = (size_t)row * 32 + c4 * 2;
    *(uint2*)(g_Fh + w) = make_uint2(pack_bf16x2(hx, hy), pack_bf16x2(hz, hw));
    *(uint2*)(g_Fm + w) = make_uint2(pack_bf16x2(mx, my), pack_bf16x2(mz, mw));
}

// ---------------------------------------------------------------------------
// K1: KNN via radius filter + exact rank-select fallback (unchanged; correct).
// ---------------------------------------------------------------------------
__global__ __launch_bounds__(256) void knn_kernel(const float* __restrict__ points)
{
    __shared__ float sp[N_ * 3];
    __shared__ float sd2[8][256];
    __shared__ int   sidx[8][256];

    const int b = blockIdx.y;
    const float* pb = points + (size_t)b * N_ * 3;
    for (int i = threadIdx.x; i < N_ * 3; i += 256) sp[i] = pb[i];
    __syncthreads();

    const int warp = threadIdx.x >> 5;
    const int lane = threadIdx.x & 31;
    const int m = blockIdx.x * 8 + warp;
    const int src = m * 4;

    const float tx = sp[src * 3 + 0];
    const float ty = sp[src * 3 + 1];
    const float tz = sp[src * 3 + 2];

    const float TH = 0.16f * 1.00002f;

    int base = 0;
    for (int c = lane; c < N_; c += 32) {
        float dx = sp[c * 3 + 0] - tx;
        float dy = sp[c * 3 + 1] - ty;
        float dz = sp[c * 3 + 2] - tz;
        float d2 = dx * dx + dy * dy + dz * dz;
        bool p = (d2 <= TH);
        unsigned msk = __ballot_sync(0xffffffffu, p);
        if (p) {
            int pos = base + __popc(msk & ((1u << lane) - 1u));
            if (pos < 256) { sd2[warp][pos] = d2; sidx[warp][pos] = c; }
        }
        base += __popc(msk);
    }
    int cnt = min(base, 256);
    __syncwarp();

    int* out = g_nbr + (size_t)(b * M_ + m) * KNN_;
    if (cnt <= KNN_) {
        out[lane] = (lane < cnt) ? sidx[warp][lane] : -1;
    } else {
        for (int i = lane; i < cnt; i += 32) {
            float di = sd2[warp][i];
            int rank = 0;
            for (int jj = 0; jj < cnt; jj++) {
                float dj = sd2[warp][jj];
                rank += (dj < di) || (dj == di && jj < i);
            }
            if (rank < KNN_) out[rank] = sidx[warp][i];
        }
    }
}

// ---------------------------------------------------------------------------
// K2: A = feats @ W via mma.sync.m16n8k16 bf16, 3xBF16 (hi*hi + hi*mid + mid*hi).
// Block tile 128x64, warp tile 32x32 (8 warps = 4M x 2N), single K=64 pass.
// Both operands pre-split in global -> fills are straight uint4 copies.
// ---------------------------------------------------------------------------
#define GBM 128
#define GBN 64
#define KW  32          // K in bf16x2 words (64 halves)
#define STR 36          // 32 + 4 pad: banks (4*row + pair) all distinct

__device__ __forceinline__ void mma_bf16(float* d, const uint32_t* a, const uint32_t* b)
{
    asm volatile(
        "mma.sync.aligned.m16n8k16.row.col.f32.bf16.bf16.f32 "
        "{%0,%1,%2,%3},{%4,%5,%6,%7},{%8,%9},{%0,%1,%2,%3};\n"
        : "+f"(d[0]), "+f"(d[1]), "+f"(d[2]), "+f"(d[3])
        : "r"(a[0]), "r"(a[1]), "r"(a[2]), "r"(a[3]), "r"(b[0]), "r"(b[1]));
}

__global__ __launch_bounds__(256, 3) void gemm_tc_kernel()
{
    extern __shared__ uint32_t smem_g[];
    uint32_t* Ah = smem_g;                 // [GBM][STR]
    uint32_t* Am = Ah + GBM * STR;         // [GBM][STR]
    uint32_t* Bh = Am + GBM * STR;         // [GBN][STR]
    uint32_t* Bm = Bh + GBN * STR;         // [GBN][STR]

    const int tid  = threadIdx.x;
    const int warp = tid >> 5;
    const int lane = tid & 31;
    const int wm   = warp & 3;     // 0..3 (M)
    const int wn   = warp >> 2;    // 0..1 (N)
    const int r0   = blockIdx.x * GBM;
    const int j0   = blockIdx.y * GBN;

    // ---- A fill: 128 rows x 8 uint4 per row = 1024 uint4 per array ----
#pragma unroll
    for (int it = 0; it < 4; it++) {
        int idx = tid + it * 256;          // 0..1023
        int r  = idx >> 3;
        int p4 = idx & 7;
        size_t gsrc = (size_t)(r0 + r) * KW + p4 * 4;
        *(uint4*)(Ah + r * STR + p4 * 4) = *(const uint4*)(g_Fh + gsrc);
        *(uint4*)(Am + r * STR + p4 * 4) = *(const uint4*)(g_Fm + gsrc);
    }
    // ---- B fill: 64 n-rows x 8 uint4 = 512 uint4 per array ----
#pragma unroll
    for (int it = 0; it < 2; it++) {
        int idx = tid + it * 256;          // 0..511
        int n  = idx >> 3;
        int p4 = idx & 7;
        size_t gsrc = (size_t)(j0 + n) * KW + p4 * 4;
        *(uint4*)(Bh + n * STR + p4 * 4) = *(const uint4*)(g_Wh + gsrc);
        *(uint4*)(Bm + n * STR + p4 * 4) = *(const uint4*)(g_Wm + gsrc);
    }
    __syncthreads();

    float acc[2][4][4];
#pragma unroll
    for (int mt = 0; mt < 2; mt++)
#pragma unroll
        for (int nt = 0; nt < 4; nt++)
#pragma unroll
            for (int i = 0; i < 4; i++) acc[mt][nt][i] = 0.0f;

#pragma unroll
    for (int ks = 0; ks < 4; ks++) {                 // 4 x k16 steps
        const int bp = ks * 8 + (lane & 3);          // base k-pair
        uint32_t ah[2][4], am[2][4];
#pragma unroll
        for (int mt = 0; mt < 2; mt++) {
            int row = wm * 32 + mt * 16 + (lane >> 2);
            ah[mt][0] = Ah[row * STR + bp];
            ah[mt][1] = Ah[(row + 8) * STR + bp];
            ah[mt][2] = Ah[row * STR + bp + 4];
            ah[mt][3] = Ah[(row + 8) * STR + bp + 4];
            am[mt][0] = Am[row * STR + bp];
            am[mt][1] = Am[(row + 8) * STR + bp];
            am[mt][2] = Am[row * STR + bp + 4];
            am[mt][3] = Am[(row + 8) * STR + bp + 4];
        }
        uint32_t bh[4][2], bm[4][2];
#pragma unroll
        for (int nt = 0; nt < 4; nt++) {
            int cn = wn * 32 + nt * 8 + (lane >> 2);
            bh[nt][0] = Bh[cn * STR + bp];
            bh[nt][1] = Bh[cn * STR + bp + 4];
            bm[nt][0] = Bm[cn * STR + bp];
            bm[nt][1] = Bm[cn * STR + bp + 4];
        }
#pragma unroll
        for (int mt = 0; mt < 2; mt++)
#pragma unroll
            for (int nt = 0; nt < 4; nt++) {
                mma_bf16(acc[mt][nt], ah[mt], bh[nt]);
                mma_bf16(acc[mt][nt], am[mt], bh[nt]);
                mma_bf16(acc[mt][nt], ah[mt], bm[nt]);
            }
    }

    // Epilogue: (c0,c1)=(row, 2c..2c+1), (c2,c3)=(row+8, same cols)
#pragma unroll
    for (int mt = 0; mt < 2; mt++) {
        int row = r0 + wm * 32 + mt * 16 + (lane >> 2);
#pragma unroll
        for (int nt = 0; nt < 4; nt++) {
            int col = j0 + wn * 32 + nt * 8 + 2 * (lane & 3);
            float2 v0 = make_float2(acc[mt][nt][0], acc[mt][nt][1]);
            float2 v1 = make_float2(acc[mt][nt][2], acc[mt][nt][3]);
            *(float2*)(g_A + (size_t)row * NJ_ + col)       = v0;
            *(float2*)(g_A + (size_t)(row + 8) * NJ_ + col) = v1;
        }
    }
}

#define GEMM_SMEM ((GBM * STR * 2 + GBN * STR * 2) * 4)   // 55296 bytes

// ---------------------------------------------------------------------------
// K3: per-target TFN (R12 structure, plain launch_bounds; compacted list
// padded to multiple of 4 with exact zero-contribution dummies -> unroll 4).
// ---------------------------------------------------------------------------
__global__ __launch_bounds__(256) void tfn_kernel(const float* __restrict__ points,
                                                  const float* __restrict__ b0)
{
    __shared__ float cY[4][32][16];
    __shared__ float cW[4][32][3];
    __shared__ int   cOff[4][32];
    __shared__ int   cCnt[4];
    __shared__ float hbuf[4][64][4];

    const int tid  = threadIdx.x;
    const int warp = tid >> 5;
    const int lane = tid & 31;
    const int tBase = blockIdx.x * 4;
    const int bb = tBase >> 9;     // batch (same for all 4 targets)

    if (warp < 4) {
        const int t = tBase + warp;
        const int m = t & 511;
        const float* pb = points + (size_t)bb * N_ * 3;
        const int nb = g_nbr[(size_t)t * KNN_ + lane];

        float w0s = 0.f, w1s = 0.f, w2s = 0.f;
        float Y[16];
#pragma unroll
        for (int i = 0; i < 16; i++) Y[i] = 0.f;

        if (nb >= 0) {
            const int src = m * 4;
            float rx = pb[nb * 3 + 0] - pb[src * 3 + 0];
            float ry = pb[nb * 3 + 1] - pb[src * 3 + 1];
            float rz = pb[nb * 3 + 2] - pb[src * 3 + 2];
            float d2 = rx * rx + ry * ry + rz * rz;
            float dist = sqrtf(fmaxf(d2, 1e-12f));
            float inv = 1.0f / dist;
            float x = rx * inv, y = ry * inv, z = rz * inv;
            float x2 = x * x, y2 = y * y, z2 = z * z;
            Y[0]  = 0.282095f;
            Y[1]  = 0.488603f * y;
            Y[2]  = 0.488603f * z;
            Y[3]  = 0.488603f * x;
            Y[4]  = 1.092548f * x * y;
            Y[5]  = 1.092548f * y * z;
            Y[6]  = 0.315392f * (3.0f * z2 - 1.0f);
            Y[7]  = 1.092548f * x * z;
            Y[8]  = 0.546274f * (x2 - y2);
            Y[9]  = 0.590044f * y * (3.0f * x2 - y2);
            Y[10] = 2.890611f * x * y * z;
            Y[11] = 0.457046f * y * (5.0f * z2 - 1.0f);
            Y[12] = 0.373176f * z * (5.0f * z2 - 3.0f);
            Y[13] = 0.457046f * x * (5.0f * z2 - 1.0f);
            Y[14] = 1.445306f * z * (x2 - y2);
            Y[15] = 0.590044f * x * (x2 - 3.0f * y2);

            float dn = dist * 2.5f;            // dist / RADIUS
            if (dn <= 1.0f) {
                const float G = 6.2383246250f; // ln2 * 9
                float d1 = dn - 0.5f;
                float dq = dn - 1.0f;
                w0s = expf(-G * dn * dn);
                w1s = expf(-G * d1 * d1);
                w2s = expf(-G * dq * dq);
            }
        }

        float s0 = w0s, s1 = w1s, s2 = w2s;
#pragma unroll
        for (int d = 16; d > 0; d >>= 1) {
            s0 += __shfl_xor_sync(0xffffffffu, s0, d);
            s1 += __shfl_xor_sync(0xffffffffu, s1, d);
            s2 += __shfl_xor_sync(0xffffffffu, s2, d);
        }

        bool act = (w0s + w1s + w2s) > 0.0f;   // dn<=1 && nb>=0
        unsigned msk = __ballot_sync(0xffffffffu, act);
        int pos = __popc(msk & ((1u << lane) - 1u));
        int cnt = __popc(msk);
        int cntPad = (cnt + 3) & ~3;           // pad to multiple of 4
        if (act) {
            cOff[warp][pos] = (bb * N_ + nb) * NJ_;
            cW[warp][pos][0] = w0s / (s0 + 1e-8f);
            cW[warp][pos][1] = w1s / (s1 + 1e-8f);
            cW[warp][pos][2] = w2s / (s2 + 1e-8f);
#pragma unroll
            for (int i = 0; i < 16; i++) cY[warp][pos][i] = Y[i];
        }
        // dummy slots: offset 0, zero weights & Y -> exact zero contribution
        if (lane >= cnt && lane < cntPad) {
            cOff[warp][lane] = 0;
            cW[warp][lane][0] = 0.f;
            cW[warp][lane][1] = 0.f;
            cW[warp][lane][2] = 0.f;
#pragma unroll
            for (int i = 0; i < 16; i++) cY[warp][lane][i] = 0.f;
        }
        if (lane == 0) cCnt[warp] = cntPad;
    }
    __syncthreads();

    const int tg = tid >> 6;          // target within block
    const int j  = tid & 63;
    const int l  = j >> 4;            // slab
    const int u0 = (j & 15) << 2;     // 4 units per thread
    const int baser = l * l;
    const int nr = 2 * l + 1;
    const int cnt = cCnt[tg];

    float ax[7], ay[7], az[7], aw[7];
#pragma unroll
    for (int r = 0; r < 7; r++) { ax[r] = 0.f; ay[r] = 0.f; az[r] = 0.f; aw[r] = 0.f; }

    const float* Abase = g_A + l * 192 + u0;
#pragma unroll 4
    for (int k = 0; k < cnt; k++) {
        const float* Ar = Abase + cOff[tg][k];
        float4 A0 = *(const float4*)(Ar);
        float4 A1 = *(const float4*)(Ar + 64);
        float4 A2 = *(const float4*)(Ar + 128);
        float w0 = cW[tg][k][0], w1 = cW[tg][k][1], w2 = cW[tg][k][2];
        float gx = w0 * A0.x + w1 * A1.x + w2 * A2.x;
        float gy = w0 * A0.y + w1 * A1.y + w2 * A2.y;
        float gz = w0 * A0.z + w1 * A1.z + w2 * A2.z;
        float gw = w0 * A0.w + w1 * A1.w + w2 * A2.w;
        const float* Yk = &cY[tg][k][baser];
#pragma unroll
        for (int r = 0; r < 7; r++)
            if (r < nr) {
                float y = Yk[r];
                ax[r] += y * gx; ay[r] += y * gy;
                az[r] += y * gz; aw[r] += y * gw;
            }
    }

    if (l == 0) {
        ax[0] += b0[u0 + 0]; ay[0] += b0[u0 + 1];
        az[0] += b0[u0 + 2]; aw[0] += b0[u0 + 3];
    }

    float sx = 0.f, sy = 0.f, sz = 0.f, sw = 0.f;
#pragma unroll
    for (int r = 0; r < 7; r++)
        if (r < nr) {
            sx += ax[r] * ax[r]; sy += ay[r] * ay[r];
            sz += az[r] * az[r]; sw += aw[r] * aw[r];
        }
    hbuf[tg][j][0] = sqrtf(fmaxf(sx, 1e-8f));
    hbuf[tg][j][1] = sqrtf(fmaxf(sy, 1e-8f));
    hbuf[tg][j][2] = sqrtf(fmaxf(sz, 1e-8f));
    hbuf[tg][j][3] = sqrtf(fmaxf(sw, 1e-8f));
    __syncthreads();

    {
        int jj = tid >> 2;            // 0..63
        int cc = tid & 3;             // 0..3
        float h = fmaxf(fmaxf(hbuf[0][jj][cc], hbuf[1][jj][cc]),
                        fmaxf(hbuf[2][jj][cc], hbuf[3][jj][cc]));
        int ll = jj >> 4;
        int uu = ((jj & 15) << 2) + cc;
        // h > 0 always, so int-compare == float-compare
        atomicMax((int*)&g_H[bb * 256 + ll * 64 + uu], __float_as_int(h));
    }
}

// ---------------------------------------------------------------------------
// K4: MLP head + softmax, float4 weight loads, full-block k-split partials.
// ---------------------------------------------------------------------------
__global__ __launch_bounds__(256) void mlp_kernel(
    const float* __restrict__ Wfc1, const float* __restrict__ bfc1,
    const float* __restrict__ Wfc2, const float* __restrict__ bfc2,
    const float* __restrict__ Wsm,  const float* __restrict__ bsm,
    float* __restrict__ out)
{
    __shared__ float  sH[256];
    __shared__ float4 part[256];
    __shared__ float  s1[512];
    __shared__ float  s2[256];
    __shared__ float  sl[40];

    const int b = blockIdx.x;
    const int t = threadIdx.x;

    sH[t] = g_H[b * 256 + t];
    __syncthreads();

    {
        const int u4 = t & 127;
        const int k0 = (t >> 7) * 128;
        const float4* W4 = (const float4*)Wfc1;   // [k][128]
        float4 a = make_float4(0.f, 0.f, 0.f, 0.f);
#pragma unroll 4
        for (int k = k0; k < k0 + 128; k++) {
            float h = sH[k];
            float4 w = W4[k * 128 + u4];
            a.x += h * w.x; a.y += h * w.y; a.z += h * w.z; a.w += h * w.w;
        }
        part[t] = a;
    }
    __syncthreads();
    if (t < 128) {
        float4 a = part[t], c = part[t + 128];
        float4 bias = ((const float4*)bfc1)[t];
        float4 r;
        r.x = fmaxf(a.x + c.x + bias.x, 0.f);
        r.y = fmaxf(a.y + c.y + bias.y, 0.f);
        r.z = fmaxf(a.z + c.z + bias.z, 0.f);
        r.w = fmaxf(a.w + c.w + bias.w, 0.f);
        ((float4*)s1)[t] = r;
    }
    __syncthreads();

    {
        const int u4 = t & 63;
        const int k0 = (t >> 6) * 128;
        const float4* W4 = (const float4*)Wfc2;   // [k][64]
        float4 a = make_float4(0.f, 0.f, 0.f, 0.f);
#pragma unroll 4
        for (int k = k0; k < k0 + 128; k++) {
            float h = s1[k];
            float4 w = W4[k * 64 + u4];
            a.x += h * w.x; a.y += h * w.y; a.z += h * w.z; a.w += h * w.w;
        }
        part[t] = a;
    }
    __syncthreads();
    if (t < 64) {
        float4 a0 = part[t], a1 = part[t + 64], a2 = part[t + 128], a3 = part[t + 192];
        float4 bias = ((const float4*)bfc2)[t];
        float4 r;
        r.x = fmaxf(a0.x + a1.x + a2.x + a3.x + bias.x, 0.f);
        r.y = fmaxf(a0.y + a1.y + a2.y + a3.y + bias.y, 0.f);
        r.z = fmaxf(a0.z + a1.z + a2.z + a3.z + bias.z, 0.f);
        r.w = fmaxf(a0.w + a1.w + a2.w + a3.w + bias.w, 0.f);
        ((float4*)s2)[t] = r;
    }
    __syncthreads();

    if (t < 80) {
        const int u4 = t >> 3;
        const int k0 = (t & 7) * 32;
        const float4* W4 = (const float4*)Wsm;    // [k][10]
        float4 a = make_float4(0.f, 0.f, 0.f, 0.f);
#pragma unroll 4
        for (int k = k0; k < k0 + 32; k++) {
            float h = s2[k];
            float4 w = W4[k * 10 + u4];
            a.x += h * w.x; a.y += h * w.y; a.z += h * w.z; a.w += h * w.w;
        }
        part[t] = a;
    }
    __syncthreads();
    if (t < 10) {
        float4 a = make_float4(0.f, 0.f, 0.f, 0.f);
#pragma unroll
        for (int ks = 0; ks < 8; ks++) {
            float4 p = part[t * 8 + ks];
            a.x += p.x; a.y += p.y; a.z += p.z; a.w += p.w;
        }
        float4 bias = ((const float4*)bsm)[t];
        sl[t * 4 + 0] = a.x + bias.x;
        sl[t * 4 + 1] = a.y + bias.y;
        sl[t * 4 + 2] = a.z + bias.z;
        sl[t * 4 + 3] = a.w + bias.w;
    }
    __syncthreads();

    if (t == 0) {
        float mx = -1e30f;
        for (int i = 0; i < 40; i++) mx = fmaxf(mx, sl[i]);
        float s = 0.0f;
        for (int i = 0; i < 40; i++) { float e = expf(sl[i] - mx); sl[i] = e; s += e; }
        float invs = 1.0f / s;
        for (int i = 0; i < 40; i++) out[b * 40 + i] = sl[i] * invs;
    }
}

// ---------------------------------------------------------------------------
// launch
// ---------------------------------------------------------------------------
extern "C" void kernel_launch(void* const* d_in, const int* in_sizes, int n_in,
                              void* d_out, int out_size)
{
    const float* points = (const float*)d_in[0];
    const float* feats  = (const float*)d_in[1];
    const float* W0     = (const float*)d_in[2];
    const float* b0     = (const float*)d_in[3];
    const float* W1     = (const float*)d_in[4];
    const float* W2     = (const float*)d_in[5];
    const float* W3     = (const float*)d_in[6];
    const float* Wfc1   = (const float*)d_in[7];
    const float* bfc1   = (const float*)d_in[8];
    const float* Wfc2   = (const float*)d_in[9];
    const float* bfc2   = (const float*)d_in[10];
    const float* Wsm    = (const float*)d_in[11];
    const float* bsm    = (const float*)d_in[12];
    float* out = (float*)d_out;

    static bool attr_done = false;
    if (!attr_done) {
        cudaFuncSetAttribute(gemm_tc_kernel,
                             cudaFuncAttributeMaxDynamicSharedMemorySize, GEMM_SMEM);
        attr_done = true;
    }

    prep_kernel<<<96, 256>>>(W0, W1, W2, W3);
    split_feats_kernel<<<NPTS_ * 16 / 256, 256>>>(feats);
    knn_kernel<<<dim3(M_ / 8, B_), 256>>>(points);
    gemm_tc_kernel<<<dim3(NPTS_ / GBM, NJ_ / GBN), 256, GEMM_SMEM>>>();
    tfn_kernel<<<T_ / 4, 256>>>(points, b0);
    mlp_kernel<<<B_, 256>>>(Wfc1, bfc1, Wfc2, bfc2, Wsm, bsm, out);
}